// round 1
// baseline (speedup 1.0000x reference)
#include <cuda_runtime.h>
#include <cstdint>

// Problem constants (fixed by the reference)
#define NB   2
#define TT   2048
#define DD   1024
#define HH   16
#define HD   64
#define M_ROWS (NB * TT)          // 4096
#define QKV_COLS (3 * DD)         // 3072
// log2(10000)/32
#define FREQ_C 0.4152410118609203f

// Scratch (allocation-free rule: device globals)
__device__ float g_qkv[(size_t)M_ROWS * QKV_COLS];   // [N*T, 3*D]
__device__ float g_attn[(size_t)M_ROWS * DD];        // [N*T, D]

// ---------------------------------------------------------------------------
// SGEMM: C[M,N] = A[M,K] @ B[N,K]^T (+ bias[n]).  BM=BN=128, BK=8, 256 thr,
// 8x8 micro-tile per thread. All dims assumed multiples of tile sizes.
// ---------------------------------------------------------------------------
__global__ __launch_bounds__(256) void sgemm_tn(
    int M, int N, int K,
    const float* __restrict__ A, const float* __restrict__ B,
    const float* __restrict__ bias, float* __restrict__ C)
{
    __shared__ float As[8][128];
    __shared__ float Bs[8][128];

    const int tid = threadIdx.x;
    const int bx = blockIdx.x;   // N tile
    const int by = blockIdx.y;   // M tile

    const int lrow = tid >> 1;          // 0..127
    const int lc4  = (tid & 1) * 4;     // 0 or 4

    const float* Ag = A + (size_t)(by * 128 + lrow) * K + lc4;
    const float* Bg = B + (size_t)(bx * 128 + lrow) * K + lc4;

    const int ty = tid >> 4;   // 0..15
    const int tx = tid & 15;   // 0..15

    float acc[8][8];
#pragma unroll
    for (int i = 0; i < 8; i++)
#pragma unroll
        for (int j = 0; j < 8; j++) acc[i][j] = 0.f;

    for (int k0 = 0; k0 < K; k0 += 8) {
        float4 av = *(const float4*)(Ag + k0);
        float4 bv = *(const float4*)(Bg + k0);
        As[lc4 + 0][lrow] = av.x;
        As[lc4 + 1][lrow] = av.y;
        As[lc4 + 2][lrow] = av.z;
        As[lc4 + 3][lrow] = av.w;
        Bs[lc4 + 0][lrow] = bv.x;
        Bs[lc4 + 1][lrow] = bv.y;
        Bs[lc4 + 2][lrow] = bv.z;
        Bs[lc4 + 3][lrow] = bv.w;
        __syncthreads();

#pragma unroll
        for (int kk = 0; kk < 8; kk++) {
            float4 a0 = *(const float4*)&As[kk][ty * 8];
            float4 a1 = *(const float4*)&As[kk][ty * 8 + 4];
            float4 b0 = *(const float4*)&Bs[kk][tx * 8];
            float4 b1 = *(const float4*)&Bs[kk][tx * 8 + 4];
            float ar[8] = {a0.x, a0.y, a0.z, a0.w, a1.x, a1.y, a1.z, a1.w};
            float br[8] = {b0.x, b0.y, b0.z, b0.w, b1.x, b1.y, b1.z, b1.w};
#pragma unroll
            for (int i = 0; i < 8; i++)
#pragma unroll
                for (int j = 0; j < 8; j++)
                    acc[i][j] = fmaf(ar[i], br[j], acc[i][j]);
        }
        __syncthreads();
    }

    const int col0 = bx * 128 + tx * 8;
    float bb[8];
#pragma unroll
    for (int j = 0; j < 8; j++) bb[j] = bias ? bias[col0 + j] : 0.f;

#pragma unroll
    for (int i = 0; i < 8; i++) {
        const int row = by * 128 + ty * 8 + i;
        float* Cr = C + (size_t)row * N + col0;
        float4 v0 = {acc[i][0] + bb[0], acc[i][1] + bb[1],
                     acc[i][2] + bb[2], acc[i][3] + bb[3]};
        float4 v1 = {acc[i][4] + bb[4], acc[i][5] + bb[5],
                     acc[i][6] + bb[6], acc[i][7] + bb[7]};
        *(float4*)(Cr)     = v0;
        *(float4*)(Cr + 4) = v1;
    }
}

// ---------------------------------------------------------------------------
// Banded flash attention. One CTA = (batch n, head h, 64-query tile).
// RoPE applied at Q/K smem-load time. 5 key chunks of 64 cover the band.
// 256 threads: 16x16 grid, 4x4 micro-tile for S and for O.
// ---------------------------------------------------------------------------
__global__ __launch_bounds__(256) void attn_kernel(
    const float* __restrict__ qkv, float* __restrict__ out)
{
    extern __shared__ float sm[];
    float* Qt   = sm;                 // [64][64], d-major: Qt[d*64 + r]
    float* Kt   = Qt + 64 * 64;       // [64][64], d-major
    float* Vs   = Kt + 64 * 64;       // [64][64], j-major: Vs[j*64 + d]
    float* Ss   = Vs + 64 * 64;       // [64][65]
    float* m_s  = Ss + 64 * 65;       // [64]
    float* l_s  = m_s + 64;           // [64]
    float* al_s = l_s + 64;           // [64]

    const int tid = threadIdx.x;
    const int qt = blockIdx.x, h = blockIdx.y, nb = blockIdx.z;
    const int i0 = qt * 64;
    const int ty = tid >> 4, tx = tid & 15;
    const float scale = 0.125f;   // 1/sqrt(64)

    // ---- load Q tile with RoPE ----
    for (int idx = tid; idx < 64 * 32; idx += 256) {
        const int r = idx >> 5, p = idx & 31;
        const int t = i0 + r;
        const float* qrow = qkv + (size_t)(nb * TT + t) * QKV_COLS + h * HD;
        const float q1 = qrow[p], q2 = qrow[p + 32];
        const float inv = exp2f(-(float)p * FREQ_C);
        float s, c;
        sincosf((float)t * inv, &s, &c);
        Qt[p * 64 + r]        = q1 * c - q2 * s;
        Qt[(p + 32) * 64 + r] = q2 * c + q1 * s;
    }
    if (tid < 64) { m_s[tid] = -1e30f; l_s[tid] = 0.f; }

    float o[4][4];
#pragma unroll
    for (int i = 0; i < 4; i++)
#pragma unroll
        for (int j = 0; j < 4; j++) o[i][j] = 0.f;

    for (int j0 = i0 - 128; j0 <= i0 + 128; j0 += 64) {
        if (j0 + 64 <= 0 || j0 >= TT) continue;

        // ---- load K chunk (RoPE) + V chunk ----
        for (int idx = tid; idx < 64 * 32; idx += 256) {
            const int r = idx >> 5, p = idx & 31;
            const int t = j0 + r;
            float k1 = 0.f, k2 = 0.f;
            if (t >= 0 && t < TT) {
                const float* krow =
                    qkv + (size_t)(nb * TT + t) * QKV_COLS + DD + h * HD;
                k1 = krow[p]; k2 = krow[p + 32];
            }
            const float inv = exp2f(-(float)p * FREQ_C);
            float s, c;
            sincosf((float)t * inv, &s, &c);
            Kt[p * 64 + r]        = k1 * c - k2 * s;
            Kt[(p + 32) * 64 + r] = k2 * c + k1 * s;
        }
        for (int idx = tid; idx < 64 * 16; idx += 256) {
            const int r = idx >> 4, dq = (idx & 15) * 4;
            const int t = j0 + r;
            float4 v = {0.f, 0.f, 0.f, 0.f};
            if (t >= 0 && t < TT)
                v = *(const float4*)(qkv + (size_t)(nb * TT + t) * QKV_COLS +
                                     2 * DD + h * HD + dq);
            *(float4*)(Vs + r * 64 + dq) = v;
        }
        __syncthreads();

        // ---- S = Q K^T (64x64x64) ----
        float acc[4][4];
#pragma unroll
        for (int i = 0; i < 4; i++)
#pragma unroll
            for (int j = 0; j < 4; j++) acc[i][j] = 0.f;
#pragma unroll 8
        for (int d = 0; d < 64; d++) {
            float4 a = *(const float4*)(Qt + d * 64 + ty * 4);
            float4 b = *(const float4*)(Kt + d * 64 + tx * 4);
            float ar[4] = {a.x, a.y, a.z, a.w};
            float br[4] = {b.x, b.y, b.z, b.w};
#pragma unroll
            for (int i = 0; i < 4; i++)
#pragma unroll
                for (int j = 0; j < 4; j++)
                    acc[i][j] = fmaf(ar[i], br[j], acc[i][j]);
        }
        // scale + band mask -> Ss
#pragma unroll
        for (int i = 0; i < 4; i++) {
            const int ii = i0 + ty * 4 + i;
#pragma unroll
            for (int j = 0; j < 4; j++) {
                const int jj = j0 + tx * 4 + j;
                const bool valid = (jj >= 0) && (jj < TT) &&
                                   (jj >= ii - 127) && (jj <= ii + 128);
                Ss[(ty * 4 + i) * 65 + tx * 4 + j] =
                    valid ? acc[i][j] * scale : -1e30f;
            }
        }
        __syncthreads();

        // ---- online softmax (one thread per query row) ----
        if (tid < 64) {
            const int r = tid;
            float mx = -1e30f;
#pragma unroll 8
            for (int c = 0; c < 64; c++) mx = fmaxf(mx, Ss[r * 65 + c]);
            const float mold = m_s[r];
            const float mnew = fmaxf(mold, mx);
            const float alpha = __expf(mold - mnew);
            float sum = 0.f;
#pragma unroll 8
            for (int c = 0; c < 64; c++) {
                const float p = __expf(Ss[r * 65 + c] - mnew);
                Ss[r * 65 + c] = p;
                sum += p;
            }
            l_s[r]  = alpha * l_s[r] + sum;
            m_s[r]  = mnew;
            al_s[r] = alpha;
        }
        __syncthreads();

        // ---- O = alpha*O + P V ----
        {
            float al[4];
#pragma unroll
            for (int i = 0; i < 4; i++) al[i] = al_s[ty * 4 + i];
#pragma unroll
            for (int i = 0; i < 4; i++)
#pragma unroll
                for (int j = 0; j < 4; j++) o[i][j] *= al[i];
#pragma unroll 8
            for (int j = 0; j < 64; j++) {
                float4 v = *(const float4*)(Vs + j * 64 + tx * 4);
                float pr[4];
#pragma unroll
                for (int i = 0; i < 4; i++) pr[i] = Ss[(ty * 4 + i) * 65 + j];
#pragma unroll
                for (int i = 0; i < 4; i++) {
                    o[i][0] = fmaf(pr[i], v.x, o[i][0]);
                    o[i][1] = fmaf(pr[i], v.y, o[i][1]);
                    o[i][2] = fmaf(pr[i], v.z, o[i][2]);
                    o[i][3] = fmaf(pr[i], v.w, o[i][3]);
                }
            }
        }
        __syncthreads();   // protect Kt/Vs/Ss before next chunk
    }

    // ---- normalize + write out [N,T,D], D index = h*64 + d ----
#pragma unroll
    for (int i = 0; i < 4; i++) {
        const int r = ty * 4 + i;
        const float invl = 1.0f / l_s[r];
        const int t = i0 + r;
        float4 res = {o[i][0] * invl, o[i][1] * invl,
                      o[i][2] * invl, o[i][3] * invl};
        *(float4*)(out + (size_t)(nb * TT + t) * DD + h * HD + tx * 4) = res;
    }
}

// ---------------------------------------------------------------------------
extern "C" void kernel_launch(void* const* d_in, const int* in_sizes, int n_in,
                              void* d_out, int out_size)
{
    const float* x     = (const float*)d_in[0];  // [N,T,D]
    const float* w_qkv = (const float*)d_in[1];  // [3D,D]
    const float* w_out = (const float*)d_in[2];  // [D,D]
    const float* b_out = (const float*)d_in[3];  // [D]
    float* out = (float*)d_out;                  // [N,T,D]

    float* qkv;  cudaGetSymbolAddress((void**)&qkv,  g_qkv);
    float* attn; cudaGetSymbolAddress((void**)&attn, g_attn);

    // 1) QKV projection: [4096,3072] = x @ w_qkv^T
    {
        dim3 grid(QKV_COLS / 128, M_ROWS / 128);
        sgemm_tn<<<grid, 256>>>(M_ROWS, QKV_COLS, DD, x, w_qkv, nullptr, qkv);
    }

    // 2) Banded attention with fused RoPE
    {
        const int smem = (3 * 64 * 64 + 64 * 65 + 3 * 64) * sizeof(float); // 66560
        cudaFuncSetAttribute(attn_kernel,
                             cudaFuncAttributeMaxDynamicSharedMemorySize, smem);
        dim3 grid(TT / 64, HH, NB);
        attn_kernel<<<grid, 256, smem>>>(qkv, attn);
    }

    // 3) Output projection: out = attn @ w_out^T + b_out
    {
        dim3 grid(DD / 128, M_ROWS / 128);
        sgemm_tn<<<grid, 256>>>(M_ROWS, DD, DD, attn, w_out, b_out, out);
    }
}

// round 5
// speedup vs baseline: 1.8054x; 1.8054x over previous
#include <cuda_runtime.h>
#include <cuda_bf16.h>
#include <cstdint>

// Problem constants
#define NB   2
#define TT   2048
#define DD   1024
#define HH   16
#define HD   64
#define MR   (NB * TT)            // 4096
#define QC   (3 * DD)             // 3072
#define FREQ_C 0.4152410118609203f   // log2(10000)/32

// HMMA GEMM tiling
#define BK      32
#define ROWB    80                  // smem bytes per 32-bf16 row (padded, conflict-free)
#define TILE_B  (128 * ROWB)        // 10240 B per operand tile
#define STG     (4 * TILE_B)        // 40960 B per stage (Ah, Al, Bh, Bl)
#define GEMM_SMEM (2 * STG)         // 81920

// ------------------------------ scratch -----------------------------------
__device__ float g_qkv[(size_t)MR * QC];
__device__ __nv_bfloat16 g_xhi[(size_t)MR * DD];
__device__ __nv_bfloat16 g_xlo[(size_t)MR * DD];
__device__ __nv_bfloat16 g_wqkv_hi[(size_t)QC * DD];
__device__ __nv_bfloat16 g_wqkv_lo[(size_t)QC * DD];
__device__ __nv_bfloat16 g_wout_hi[(size_t)DD * DD];
__device__ __nv_bfloat16 g_wout_lo[(size_t)DD * DD];
__device__ __nv_bfloat16 g_ahi[(size_t)MR * DD];
__device__ __nv_bfloat16 g_alo[(size_t)MR * DD];

// --------------------------- asm helpers ----------------------------------
__device__ __forceinline__ uint32_t s2u(const void* p) {
    uint32_t a;
    asm("{ .reg .u64 t; cvta.to.shared.u64 t, %1; cvt.u32.u64 %0, t; }"
        : "=r"(a) : "l"(p));
    return a;
}
__device__ __forceinline__ void cp16(uint32_t dst, const void* src) {
    asm volatile("cp.async.cg.shared.global [%0], [%1], 16;"
                 :: "r"(dst), "l"(__cvta_generic_to_global(src)) : "memory");
}
__device__ __forceinline__ void cp_commit() {
    asm volatile("cp.async.commit_group;" ::: "memory");
}
template <int N>
__device__ __forceinline__ void cp_wait() {
    asm volatile("cp.async.wait_group %0;" :: "n"(N) : "memory");
}
__device__ __forceinline__ void ldm_x4(uint32_t& r0, uint32_t& r1,
                                       uint32_t& r2, uint32_t& r3, uint32_t a) {
    asm volatile("ldmatrix.sync.aligned.m8n8.x4.shared.b16 {%0,%1,%2,%3}, [%4];"
                 : "=r"(r0), "=r"(r1), "=r"(r2), "=r"(r3) : "r"(a));
}
__device__ __forceinline__ void mma_bf16(float* c, const uint32_t* a,
                                         const uint32_t* b) {
    asm volatile(
        "mma.sync.aligned.m16n8k16.row.col.f32.bf16.bf16.f32 "
        "{%0,%1,%2,%3}, {%4,%5,%6,%7}, {%8,%9}, {%0,%1,%2,%3};"
        : "+f"(c[0]), "+f"(c[1]), "+f"(c[2]), "+f"(c[3])
        : "r"(a[0]), "r"(a[1]), "r"(a[2]), "r"(a[3]), "r"(b[0]), "r"(b[1]));
}

// ---------------------------------------------------------------------------
// split fp32 -> (bf16 hi, bf16 lo)
// ---------------------------------------------------------------------------
__global__ __launch_bounds__(256) void split_kernel(
    const float4* __restrict__ src, __nv_bfloat162* __restrict__ hi,
    __nv_bfloat162* __restrict__ lo, int n4)
{
    int i = blockIdx.x * blockDim.x + threadIdx.x;
    if (i >= n4) return;
    float4 v = src[i];
    __nv_bfloat16 h0 = __float2bfloat16(v.x), h1 = __float2bfloat16(v.y);
    __nv_bfloat16 h2 = __float2bfloat16(v.z), h3 = __float2bfloat16(v.w);
    __nv_bfloat16 l0 = __float2bfloat16(v.x - __bfloat162float(h0));
    __nv_bfloat16 l1 = __float2bfloat16(v.y - __bfloat162float(h1));
    __nv_bfloat16 l2 = __float2bfloat16(v.z - __bfloat162float(h2));
    __nv_bfloat16 l3 = __float2bfloat16(v.w - __bfloat162float(h3));
    hi[2 * i]     = __halves2bfloat162(h0, h1);
    hi[2 * i + 1] = __halves2bfloat162(h2, h3);
    lo[2 * i]     = __halves2bfloat162(l0, l1);
    lo[2 * i + 1] = __halves2bfloat162(l2, l3);
}

// ---------------------------------------------------------------------------
// HMMA GEMM: C[M,N] = A[M,K] @ B[N,K]^T (+bias), split-bf16 3-pass.
// CTA 128x128, 8 warps (2 M x 4 N), warp tile 64x32, BK=32, cp.async 2-stage.
// ---------------------------------------------------------------------------
__global__ __launch_bounds__(256) void gemm_hmma(
    int Ng, int Kg,
    const __nv_bfloat16* __restrict__ Ahi, const __nv_bfloat16* __restrict__ Alo,
    const __nv_bfloat16* __restrict__ Bhi, const __nv_bfloat16* __restrict__ Blo,
    const float* __restrict__ bias, float* __restrict__ C)
{
    extern __shared__ char sm[];
    const uint32_t smb = s2u(sm);

    const int tid  = threadIdx.x;
    const int lane = tid & 31;
    const int wid  = tid >> 5;
    const int wm   = wid & 1;     // 0..1  (M)
    const int wn   = wid >> 1;    // 0..3  (N)
    const int m0   = blockIdx.y * 128;
    const int n0   = blockIdx.x * 128;

    // per-thread load slots: i = tid + 256*j ; row = i>>2, 16B chunk = i&3
    const int r0 = tid >> 2, c0 = (tid & 3);
    const int r1 = (tid + 256) >> 2, c1 = ((tid + 256) & 3);

    auto load_stage = [&](int st, int k0) {
        const uint32_t d0 = smb + st * STG + (uint32_t)r0 * ROWB + c0 * 16;
        const uint32_t d1 = smb + st * STG + (uint32_t)r1 * ROWB + c1 * 16;
        const size_t ga0 = (size_t)(m0 + r0) * Kg + k0 + c0 * 8;
        const size_t ga1 = (size_t)(m0 + r1) * Kg + k0 + c1 * 8;
        const size_t gb0 = (size_t)(n0 + r0) * Kg + k0 + c0 * 8;
        const size_t gb1 = (size_t)(n0 + r1) * Kg + k0 + c1 * 8;
        cp16(d0,              Ahi + ga0);  cp16(d1,              Ahi + ga1);
        cp16(d0 + TILE_B,     Alo + ga0);  cp16(d1 + TILE_B,     Alo + ga1);
        cp16(d0 + 2 * TILE_B, Bhi + gb0);  cp16(d1 + 2 * TILE_B, Bhi + gb1);
        cp16(d0 + 3 * TILE_B, Blo + gb0);  cp16(d1 + 3 * TILE_B, Blo + gb1);
    };

    float acc[4][4][4];
#pragma unroll
    for (int i = 0; i < 4; i++)
#pragma unroll
        for (int j = 0; j < 4; j++)
#pragma unroll
            for (int k = 0; k < 4; k++) acc[i][j][k] = 0.f;

    load_stage(0, 0);
    cp_commit();

    const int S = Kg / BK;
    // ldmatrix lane addressing: row = lane%16, 16B col-half = lane>>4
    const int lrow = lane & 15, lhalf = lane >> 4;

    for (int s = 0; s < S; s++) {
        if (s + 1 < S) { load_stage((s + 1) & 1, (s + 1) * BK); cp_commit(); }
        if (s + 1 < S) cp_wait<1>(); else cp_wait<0>();
        __syncthreads();

        const uint32_t stb = smb + (s & 1) * STG;
        const uint32_t aB = stb + (uint32_t)(wm * 64 + lrow) * ROWB + lhalf * 16;
        const uint32_t bB = stb + 2 * TILE_B +
                            (uint32_t)(wn * 32 + lrow) * ROWB + lhalf * 16;
#pragma unroll
        for (int k16 = 0; k16 < 2; k16++) {
            const uint32_t ko = k16 * 32;
            uint32_t ah[4][4], al[4][4], bh[4][2], bl[4][2];
#pragma unroll
            for (int mt = 0; mt < 4; mt++) {
                ldm_x4(ah[mt][0], ah[mt][1], ah[mt][2], ah[mt][3],
                       aB + ko + mt * 16 * ROWB);
                ldm_x4(al[mt][0], al[mt][1], al[mt][2], al[mt][3],
                       aB + ko + mt * 16 * ROWB + TILE_B);
            }
#pragma unroll
            for (int bt = 0; bt < 2; bt++) {
                uint32_t t0, t1, t2, t3;
                ldm_x4(t0, t1, t2, t3, bB + ko + bt * 16 * ROWB);
                bh[bt * 2][0] = t0;  bh[bt * 2][1] = t2;
                bh[bt * 2 + 1][0] = t1;  bh[bt * 2 + 1][1] = t3;
                ldm_x4(t0, t1, t2, t3, bB + ko + bt * 16 * ROWB + TILE_B);
                bl[bt * 2][0] = t0;  bl[bt * 2][1] = t2;
                bl[bt * 2 + 1][0] = t1;  bl[bt * 2 + 1][1] = t3;
            }
#pragma unroll
            for (int mt = 0; mt < 4; mt++)
#pragma unroll
                for (int nt = 0; nt < 4; nt++) {
                    mma_bf16(acc[mt][nt], ah[mt], bh[nt]);
                    mma_bf16(acc[mt][nt], ah[mt], bl[nt]);
                    mma_bf16(acc[mt][nt], al[mt], bh[nt]);
                }
        }
        __syncthreads();
    }

    // epilogue: direct fp32 stores (+bias)
    const int erow = lane >> 2, ecol = (lane & 3) * 2;
#pragma unroll
    for (int mt = 0; mt < 4; mt++) {
        const int gr = m0 + wm * 64 + mt * 16 + erow;
#pragma unroll
        for (int nt = 0; nt < 4; nt++) {
            const int gc = n0 + wn * 32 + nt * 8 + ecol;
            float b0 = 0.f, b1 = 0.f;
            if (bias) { b0 = bias[gc]; b1 = bias[gc + 1]; }
            float2 v0 = {acc[mt][nt][0] + b0, acc[mt][nt][1] + b1};
            float2 v1 = {acc[mt][nt][2] + b0, acc[mt][nt][3] + b1};
            *(float2*)(C + (size_t)gr * Ng + gc)       = v0;
            *(float2*)(C + (size_t)(gr + 8) * Ng + gc) = v1;
        }
    }
}

// ---------------------------------------------------------------------------
// Banded flash attention; epilogue emits bf16 hi/lo splits.
// ---------------------------------------------------------------------------
__global__ __launch_bounds__(256) void attn_kernel(
    const float* __restrict__ qkv,
    __nv_bfloat16* __restrict__ ohi, __nv_bfloat16* __restrict__ olo)
{
    extern __shared__ float smf[];
    float* Qt   = smf;
    float* Kt   = Qt + 64 * 64;
    float* Vs   = Kt + 64 * 64;
    float* Ss   = Vs + 64 * 64;
    float* m_s  = Ss + 64 * 65;
    float* l_s  = m_s + 64;
    float* al_s = l_s + 64;

    const int tid = threadIdx.x;
    const int qt = blockIdx.x, h = blockIdx.y, nb = blockIdx.z;
    const int i0 = qt * 64;
    const int ty = tid >> 4, tx = tid & 15;
    const float scale = 0.125f;

    for (int idx = tid; idx < 64 * 32; idx += 256) {
        const int r = idx >> 5, p = idx & 31;
        const int t = i0 + r;
        const float* qrow = qkv + (size_t)(nb * TT + t) * QC + h * HD;
        const float q1 = qrow[p], q2 = qrow[p + 32];
        const float inv = exp2f(-(float)p * FREQ_C);
        float s, c;
        sincosf((float)t * inv, &s, &c);
        Qt[p * 64 + r]        = q1 * c - q2 * s;
        Qt[(p + 32) * 64 + r] = q2 * c + q1 * s;
    }
    if (tid < 64) { m_s[tid] = -1e30f; l_s[tid] = 0.f; }

    float o[4][4];
#pragma unroll
    for (int i = 0; i < 4; i++)
#pragma unroll
        for (int j = 0; j < 4; j++) o[i][j] = 0.f;

    for (int j0 = i0 - 128; j0 <= i0 + 128; j0 += 64) {
        if (j0 + 64 <= 0 || j0 >= TT) continue;

        for (int idx = tid; idx < 64 * 32; idx += 256) {
            const int r = idx >> 5, p = idx & 31;
            const int t = j0 + r;
            float k1 = 0.f, k2 = 0.f;
            if (t >= 0 && t < TT) {
                const float* krow = qkv + (size_t)(nb * TT + t) * QC + DD + h * HD;
                k1 = krow[p]; k2 = krow[p + 32];
            }
            const float inv = exp2f(-(float)p * FREQ_C);
            float s, c;
            sincosf((float)t * inv, &s, &c);
            Kt[p * 64 + r]        = k1 * c - k2 * s;
            Kt[(p + 32) * 64 + r] = k2 * c + k1 * s;
        }
        for (int idx = tid; idx < 64 * 16; idx += 256) {
            const int r = idx >> 4, dq = (idx & 15) * 4;
            const int t = j0 + r;
            float4 v = {0.f, 0.f, 0.f, 0.f};
            if (t >= 0 && t < TT)
                v = *(const float4*)(qkv + (size_t)(nb * TT + t) * QC +
                                     2 * DD + h * HD + dq);
            *(float4*)(Vs + r * 64 + dq) = v;
        }
        __syncthreads();

        float acc[4][4];
#pragma unroll
        for (int i = 0; i < 4; i++)
#pragma unroll
            for (int j = 0; j < 4; j++) acc[i][j] = 0.f;
#pragma unroll 8
        for (int d = 0; d < 64; d++) {
            float4 a = *(const float4*)(Qt + d * 64 + ty * 4);
            float4 b = *(const float4*)(Kt + d * 64 + tx * 4);
            float ar[4] = {a.x, a.y, a.z, a.w};
            float br[4] = {b.x, b.y, b.z, b.w};
#pragma unroll
            for (int i = 0; i < 4; i++)
#pragma unroll
                for (int j = 0; j < 4; j++)
                    acc[i][j] = fmaf(ar[i], br[j], acc[i][j]);
        }
#pragma unroll
        for (int i = 0; i < 4; i++) {
            const int ii = i0 + ty * 4 + i;
#pragma unroll
            for (int j = 0; j < 4; j++) {
                const int jj = j0 + tx * 4 + j;
                const bool valid = (jj >= 0) && (jj < TT) &&
                                   (jj >= ii - 127) && (jj <= ii + 128);
                Ss[(ty * 4 + i) * 65 + tx * 4 + j] =
                    valid ? acc[i][j] * scale : -1e30f;
            }
        }
        __syncthreads();

        if (tid < 64) {
            const int r = tid;
            float mx = -1e30f;
#pragma unroll 8
            for (int c = 0; c < 64; c++) mx = fmaxf(mx, Ss[r * 65 + c]);
            const float mold = m_s[r];
            const float mnew = fmaxf(mold, mx);
            const float alpha = __expf(mold - mnew);
            float sum = 0.f;
#pragma unroll 8
            for (int c = 0; c < 64; c++) {
                const float p = __expf(Ss[r * 65 + c] - mnew);
                Ss[r * 65 + c] = p;
                sum += p;
            }
            l_s[r]  = alpha * l_s[r] + sum;
            m_s[r]  = mnew;
            al_s[r] = alpha;
        }
        __syncthreads();

        {
            float al[4];
#pragma unroll
            for (int i = 0; i < 4; i++) al[i] = al_s[ty * 4 + i];
#pragma unroll
            for (int i = 0; i < 4; i++)
#pragma unroll
                for (int j = 0; j < 4; j++) o[i][j] *= al[i];
#pragma unroll 8
            for (int j = 0; j < 64; j++) {
                float4 v = *(const float4*)(Vs + j * 64 + tx * 4);
                float pr[4];
#pragma unroll
                for (int i = 0; i < 4; i++) pr[i] = Ss[(ty * 4 + i) * 65 + j];
#pragma unroll
                for (int i = 0; i < 4; i++) {
                    o[i][0] = fmaf(pr[i], v.x, o[i][0]);
                    o[i][1] = fmaf(pr[i], v.y, o[i][1]);
                    o[i][2] = fmaf(pr[i], v.z, o[i][2]);
                    o[i][3] = fmaf(pr[i], v.w, o[i][3]);
                }
            }
        }
        __syncthreads();
    }

#pragma unroll
    for (int i = 0; i < 4; i++) {
        const int r = ty * 4 + i;
        const float invl = 1.0f / l_s[r];
        const int t = i0 + r;
        const size_t base = (size_t)(nb * TT + t) * DD + h * HD + tx * 4;
#pragma unroll
        for (int j = 0; j < 4; j++) {
            const float val = o[i][j] * invl;
            const __nv_bfloat16 hh = __float2bfloat16(val);
            ohi[base + j] = hh;
            olo[base + j] = __float2bfloat16(val - __bfloat162float(hh));
        }
    }
}

// ---------------------------------------------------------------------------
extern "C" void kernel_launch(void* const* d_in, const int* in_sizes, int n_in,
                              void* d_out, int out_size)
{
    const float* x     = (const float*)d_in[0];
    const float* w_qkv = (const float*)d_in[1];
    const float* w_out = (const float*)d_in[2];
    const float* b_out = (const float*)d_in[3];
    float* out = (float*)d_out;

    float* qkv;  cudaGetSymbolAddress((void**)&qkv, g_qkv);
    __nv_bfloat16 *xhi, *xlo, *wqh, *wql, *woh, *wol, *ahi, *alo;
    cudaGetSymbolAddress((void**)&xhi, g_xhi);
    cudaGetSymbolAddress((void**)&xlo, g_xlo);
    cudaGetSymbolAddress((void**)&wqh, g_wqkv_hi);
    cudaGetSymbolAddress((void**)&wql, g_wqkv_lo);
    cudaGetSymbolAddress((void**)&woh, g_wout_hi);
    cudaGetSymbolAddress((void**)&wol, g_wout_lo);
    cudaGetSymbolAddress((void**)&ahi, g_ahi);
    cudaGetSymbolAddress((void**)&alo, g_alo);

    cudaFuncSetAttribute(gemm_hmma,
                         cudaFuncAttributeMaxDynamicSharedMemorySize, GEMM_SMEM);
    cudaFuncSetAttribute(attn_kernel,
                         cudaFuncAttributeMaxDynamicSharedMemorySize, 66560);

    // 1) split inputs / weights to bf16 hi/lo
    {
        int n4 = MR * DD / 4;
        split_kernel<<<(n4 + 255) / 256, 256>>>(
            (const float4*)x, (__nv_bfloat162*)xhi, (__nv_bfloat162*)xlo, n4);
        n4 = QC * DD / 4;
        split_kernel<<<(n4 + 255) / 256, 256>>>(
            (const float4*)w_qkv, (__nv_bfloat162*)wqh, (__nv_bfloat162*)wql, n4);
        n4 = DD * DD / 4;
        split_kernel<<<(n4 + 255) / 256, 256>>>(
            (const float4*)w_out, (__nv_bfloat162*)woh, (__nv_bfloat162*)wol, n4);
    }

    // 2) QKV projection (HMMA): [4096,3072] fp32
    {
        dim3 grid(QC / 128, MR / 128);
        gemm_hmma<<<grid, 256, GEMM_SMEM>>>(QC, DD, xhi, xlo, wqh, wql,
                                            nullptr, qkv);
    }

    // 3) banded attention + fused RoPE; writes bf16 hi/lo directly
    {
        dim3 grid(TT / 64, HH, NB);
        attn_kernel<<<grid, 256, 66560>>>(qkv, ahi, alo);
    }

    // 4) output projection (HMMA) + bias -> fp32 out
    {
        dim3 grid(DD / 128, MR / 128);
        gemm_hmma<<<grid, 256, GEMM_SMEM>>>(DD, DD, ahi, alo, woh, wol,
                                            b_out, out);
    }
}

// round 6
// speedup vs baseline: 2.3550x; 1.3045x over previous
#include <cuda_runtime.h>
#include <cuda_bf16.h>
#include <cstdint>

// Problem constants
#define NB   2
#define TT   2048
#define DD   1024
#define HH   16
#define HD   64
#define MR   (NB * TT)            // 4096
#define QC   (3 * DD)             // 3072
#define FREQ_C 0.4152410118609203f   // log2(10000)/32

// HMMA GEMM tiling
#define BK      32
#define ROWB    80
#define TILE_B  (128 * ROWB)
#define STG     (4 * TILE_B)
#define GEMM_SMEM (2 * STG)

// attention smem pitches
#define KP   144                  // 64-bf16 row + 16B pad
#define VP   272                  // 128-bf16 row + 16B pad
#define SM_KH 0
#define SM_KL 18432
#define SM_VH 36864
#define SM_VL 54272
#define ATTN_SMEM 71680

// ------------------------------ scratch -----------------------------------
__device__ __align__(128) float g_qkv[(size_t)MR * QC];
__device__ __align__(128) __nv_bfloat16 g_xhi[(size_t)MR * DD];
__device__ __align__(128) __nv_bfloat16 g_xlo[(size_t)MR * DD];
__device__ __align__(128) __nv_bfloat16 g_wqkv_hi[(size_t)QC * DD];
__device__ __align__(128) __nv_bfloat16 g_wqkv_lo[(size_t)QC * DD];
__device__ __align__(128) __nv_bfloat16 g_wout_hi[(size_t)DD * DD];
__device__ __align__(128) __nv_bfloat16 g_wout_lo[(size_t)DD * DD];
__device__ __align__(128) __nv_bfloat16 g_ahi[(size_t)MR * DD];
__device__ __align__(128) __nv_bfloat16 g_alo[(size_t)MR * DD];
// rope'd / split attention operands, head-major
__device__ __align__(128) __nv_bfloat16 g_qh[(size_t)NB * HH * TT * HD];
__device__ __align__(128) __nv_bfloat16 g_ql[(size_t)NB * HH * TT * HD];
__device__ __align__(128) __nv_bfloat16 g_kh[(size_t)NB * HH * TT * HD];
__device__ __align__(128) __nv_bfloat16 g_kl[(size_t)NB * HH * TT * HD];
__device__ __align__(128) __nv_bfloat16 g_vth[(size_t)NB * HH * HD * TT];
__device__ __align__(128) __nv_bfloat16 g_vtl[(size_t)NB * HH * HD * TT];

// --------------------------- asm helpers ----------------------------------
__device__ __forceinline__ uint32_t s2u(const void* p) {
    uint32_t a;
    asm("{ .reg .u64 t; cvta.to.shared.u64 t, %1; cvt.u32.u64 %0, t; }"
        : "=r"(a) : "l"(p));
    return a;
}
__device__ __forceinline__ void cp16(uint32_t dst, const void* src) {
    asm volatile("cp.async.cg.shared.global [%0], [%1], 16;"
                 :: "r"(dst), "l"(__cvta_generic_to_global(src)) : "memory");
}
__device__ __forceinline__ void cp_commit() {
    asm volatile("cp.async.commit_group;" ::: "memory");
}
template <int N>
__device__ __forceinline__ void cp_wait() {
    asm volatile("cp.async.wait_group %0;" :: "n"(N) : "memory");
}
__device__ __forceinline__ void ldm_x4(uint32_t& r0, uint32_t& r1,
                                       uint32_t& r2, uint32_t& r3, uint32_t a) {
    asm volatile("ldmatrix.sync.aligned.m8n8.x4.shared.b16 {%0,%1,%2,%3}, [%4];"
                 : "=r"(r0), "=r"(r1), "=r"(r2), "=r"(r3) : "r"(a));
}
__device__ __forceinline__ void mma_bf16(float* c, const uint32_t* a,
                                         const uint32_t* b) {
    asm volatile(
        "mma.sync.aligned.m16n8k16.row.col.f32.bf16.bf16.f32 "
        "{%0,%1,%2,%3}, {%4,%5,%6,%7}, {%8,%9}, {%0,%1,%2,%3};"
        : "+f"(c[0]), "+f"(c[1]), "+f"(c[2]), "+f"(c[3])
        : "r"(a[0]), "r"(a[1]), "r"(a[2]), "r"(a[3]), "r"(b[0]), "r"(b[1]));
}
__device__ __forceinline__ void split1(float v, __nv_bfloat16& h, __nv_bfloat16& l) {
    h = __float2bfloat16(v);
    l = __float2bfloat16(v - __bfloat162float(h));
}
// pack two floats to bf16x2 (hi) and residual bf16x2 (lo)
__device__ __forceinline__ void packbf(float a, float b, uint32_t& hi, uint32_t& lo) {
    __nv_bfloat162 h = __floats2bfloat162_rn(a, b);
    __nv_bfloat162 l = __floats2bfloat162_rn(a - __bfloat162float(h.x),
                                             b - __bfloat162float(h.y));
    hi = *reinterpret_cast<uint32_t*>(&h);
    lo = *reinterpret_cast<uint32_t*>(&l);
}

// ---------------------------------------------------------------------------
// split fp32 -> (bf16 hi, bf16 lo)
// ---------------------------------------------------------------------------
__global__ __launch_bounds__(256) void split_kernel(
    const float4* __restrict__ src, __nv_bfloat162* __restrict__ hi,
    __nv_bfloat162* __restrict__ lo, int n4)
{
    int i = blockIdx.x * blockDim.x + threadIdx.x;
    if (i >= n4) return;
    float4 v = src[i];
    __nv_bfloat16 h0, h1, h2, h3, l0, l1, l2, l3;
    split1(v.x, h0, l0); split1(v.y, h1, l1);
    split1(v.z, h2, l2); split1(v.w, h3, l3);
    hi[2 * i]     = __halves2bfloat162(h0, h1);
    hi[2 * i + 1] = __halves2bfloat162(h2, h3);
    lo[2 * i]     = __halves2bfloat162(l0, l1);
    lo[2 * i + 1] = __halves2bfloat162(l2, l3);
}

// ---------------------------------------------------------------------------
// HMMA GEMM (unchanged from R5 winner)
// ---------------------------------------------------------------------------
__global__ __launch_bounds__(256) void gemm_hmma(
    int Ng, int Kg,
    const __nv_bfloat16* __restrict__ Ahi, const __nv_bfloat16* __restrict__ Alo,
    const __nv_bfloat16* __restrict__ Bhi, const __nv_bfloat16* __restrict__ Blo,
    const float* __restrict__ bias, float* __restrict__ C)
{
    extern __shared__ char sm[];
    const uint32_t smb = s2u(sm);

    const int tid  = threadIdx.x;
    const int lane = tid & 31;
    const int wid  = tid >> 5;
    const int wm   = wid & 1;
    const int wn   = wid >> 1;
    const int m0   = blockIdx.y * 128;
    const int n0   = blockIdx.x * 128;

    const int r0 = tid >> 2, c0 = (tid & 3);
    const int r1 = (tid + 256) >> 2, c1 = ((tid + 256) & 3);

    auto load_stage = [&](int st, int k0) {
        const uint32_t d0 = smb + st * STG + (uint32_t)r0 * ROWB + c0 * 16;
        const uint32_t d1 = smb + st * STG + (uint32_t)r1 * ROWB + c1 * 16;
        const size_t ga0 = (size_t)(m0 + r0) * Kg + k0 + c0 * 8;
        const size_t ga1 = (size_t)(m0 + r1) * Kg + k0 + c1 * 8;
        const size_t gb0 = (size_t)(n0 + r0) * Kg + k0 + c0 * 8;
        const size_t gb1 = (size_t)(n0 + r1) * Kg + k0 + c1 * 8;
        cp16(d0,              Ahi + ga0);  cp16(d1,              Ahi + ga1);
        cp16(d0 + TILE_B,     Alo + ga0);  cp16(d1 + TILE_B,     Alo + ga1);
        cp16(d0 + 2 * TILE_B, Bhi + gb0);  cp16(d1 + 2 * TILE_B, Bhi + gb1);
        cp16(d0 + 3 * TILE_B, Blo + gb0);  cp16(d1 + 3 * TILE_B, Blo + gb1);
    };

    float acc[4][4][4];
#pragma unroll
    for (int i = 0; i < 4; i++)
#pragma unroll
        for (int j = 0; j < 4; j++)
#pragma unroll
            for (int k = 0; k < 4; k++) acc[i][j][k] = 0.f;

    load_stage(0, 0);
    cp_commit();

    const int S = Kg / BK;
    const int lrow = lane & 15, lhalf = lane >> 4;

    for (int s = 0; s < S; s++) {
        if (s + 1 < S) { load_stage((s + 1) & 1, (s + 1) * BK); cp_commit(); }
        if (s + 1 < S) cp_wait<1>(); else cp_wait<0>();
        __syncthreads();

        const uint32_t stb = smb + (s & 1) * STG;
        const uint32_t aB = stb + (uint32_t)(wm * 64 + lrow) * ROWB + lhalf * 16;
        const uint32_t bB = stb + 2 * TILE_B +
                            (uint32_t)(wn * 32 + lrow) * ROWB + lhalf * 16;
#pragma unroll
        for (int k16 = 0; k16 < 2; k16++) {
            const uint32_t ko = k16 * 32;
            uint32_t ah[4][4], al[4][4], bh[4][2], bl[4][2];
#pragma unroll
            for (int mt = 0; mt < 4; mt++) {
                ldm_x4(ah[mt][0], ah[mt][1], ah[mt][2], ah[mt][3],
                       aB + ko + mt * 16 * ROWB);
                ldm_x4(al[mt][0], al[mt][1], al[mt][2], al[mt][3],
                       aB + ko + mt * 16 * ROWB + TILE_B);
            }
#pragma unroll
            for (int bt = 0; bt < 2; bt++) {
                uint32_t t0, t1, t2, t3;
                ldm_x4(t0, t1, t2, t3, bB + ko + bt * 16 * ROWB);
                bh[bt * 2][0] = t0;  bh[bt * 2][1] = t2;
                bh[bt * 2 + 1][0] = t1;  bh[bt * 2 + 1][1] = t3;
                ldm_x4(t0, t1, t2, t3, bB + ko + bt * 16 * ROWB + TILE_B);
                bl[bt * 2][0] = t0;  bl[bt * 2][1] = t2;
                bl[bt * 2 + 1][0] = t1;  bl[bt * 2 + 1][1] = t3;
            }
#pragma unroll
            for (int mt = 0; mt < 4; mt++)
#pragma unroll
                for (int nt = 0; nt < 4; nt++) {
                    mma_bf16(acc[mt][nt], ah[mt], bh[nt]);
                    mma_bf16(acc[mt][nt], ah[mt], bl[nt]);
                    mma_bf16(acc[mt][nt], al[mt], bh[nt]);
                }
        }
        __syncthreads();
    }

    const int erow = lane >> 2, ecol = (lane & 3) * 2;
#pragma unroll
    for (int mt = 0; mt < 4; mt++) {
        const int gr = m0 + wm * 64 + mt * 16 + erow;
#pragma unroll
        for (int nt = 0; nt < 4; nt++) {
            const int gc = n0 + wn * 32 + nt * 8 + ecol;
            float b0 = 0.f, b1 = 0.f;
            if (bias) { b0 = bias[gc]; b1 = bias[gc + 1]; }
            float2 v0 = {acc[mt][nt][0] + b0, acc[mt][nt][1] + b1};
            float2 v1 = {acc[mt][nt][2] + b0, acc[mt][nt][3] + b1};
            *(float2*)(C + (size_t)gr * Ng + gc)       = v0;
            *(float2*)(C + (size_t)(gr + 8) * Ng + gc) = v1;
        }
    }
}

// ---------------------------------------------------------------------------
// prep 1: RoPE + scale(Q) + split -> head-major Qh/Ql/Kh/Kl [nb][h][t][64]
// ---------------------------------------------------------------------------
__global__ __launch_bounds__(256) void rope_split_qk(
    const float* __restrict__ qkv,
    __nv_bfloat16* __restrict__ Qh, __nv_bfloat16* __restrict__ Ql,
    __nv_bfloat16* __restrict__ Kh, __nv_bfloat16* __restrict__ Kl)
{
    const int t0 = blockIdx.x * 64, h = blockIdx.y, nb = blockIdx.z;
    for (int idx = threadIdx.x; idx < 64 * 32; idx += 256) {
        const int tl = idx >> 5, p = idx & 31;
        const int t = t0 + tl;
        const float inv = exp2f(-(float)p * FREQ_C);
        float s, c;
        sincosf((float)t * inv, &s, &c);

        const size_t src = (size_t)(nb * TT + t) * QC + h * HD;
        const size_t dst = ((size_t)(nb * HH + h) * TT + t) * HD;

        const float q1 = qkv[src + p], q2 = qkv[src + p + 32];
        const float qa = (q1 * c - q2 * s) * 0.125f;
        const float qb = (q2 * c + q1 * s) * 0.125f;
        __nv_bfloat16 hh, ll;
        split1(qa, hh, ll);  Qh[dst + p] = hh;       Ql[dst + p] = ll;
        split1(qb, hh, ll);  Qh[dst + p + 32] = hh;  Ql[dst + p + 32] = ll;

        const float k1 = qkv[src + DD + p], k2 = qkv[src + DD + p + 32];
        const float ka = k1 * c - k2 * s;
        const float kb = k2 * c + k1 * s;
        split1(ka, hh, ll);  Kh[dst + p] = hh;       Kl[dst + p] = ll;
        split1(kb, hh, ll);  Kh[dst + p + 32] = hh;  Kl[dst + p + 32] = ll;
    }
}

// ---------------------------------------------------------------------------
// prep 2: V transpose + split -> Vt [nb][h][d][t]
// ---------------------------------------------------------------------------
__global__ __launch_bounds__(256) void vtrans_split(
    const float* __restrict__ qkv,
    __nv_bfloat16* __restrict__ Vth, __nv_bfloat16* __restrict__ Vtl)
{
    __shared__ float tile[64 * 65];
    const int t0 = blockIdx.x * 64, h = blockIdx.y, nb = blockIdx.z;
    for (int idx = threadIdx.x; idx < 64 * 64; idx += 256) {
        const int tl = idx >> 6, d = idx & 63;
        tile[tl * 65 + d] =
            qkv[(size_t)(nb * TT + t0 + tl) * QC + 2 * DD + h * HD + d];
    }
    __syncthreads();
    for (int idx = threadIdx.x; idx < 64 * 64; idx += 256) {
        const int d = idx >> 6, tl = idx & 63;
        const float v = tile[tl * 65 + d];
        __nv_bfloat16 hh, ll;
        split1(v, hh, ll);
        const size_t dst = ((size_t)(nb * HH + h) * HD + d) * TT + t0 + tl;
        Vth[dst] = hh;  Vtl[dst] = ll;
    }
}

// ---------------------------------------------------------------------------
// MMA flash attention: 128-query tile per CTA, 8 warps x 16 rows.
// 3 key chunks of 128 (diagonal first). Writes bf16 hi/lo output splits.
// ---------------------------------------------------------------------------
__global__ __launch_bounds__(256, 1) void attn_mma(
    const __nv_bfloat16* __restrict__ Qh, const __nv_bfloat16* __restrict__ Ql,
    const __nv_bfloat16* __restrict__ Kh, const __nv_bfloat16* __restrict__ Kl,
    const __nv_bfloat16* __restrict__ Vth, const __nv_bfloat16* __restrict__ Vtl,
    __nv_bfloat16* __restrict__ ohi, __nv_bfloat16* __restrict__ olo)
{
    extern __shared__ char sm[];
    const uint32_t smb = s2u(sm);

    const int tid = threadIdx.x, lane = tid & 31, w = tid >> 5;
    const int i0 = blockIdx.x * 128, h = blockIdx.y, nb = blockIdx.z;
    const size_t qkbase = (size_t)(nb * HH + h) * TT;     // row base (x64 elems)
    const size_t vbase  = (size_t)(nb * HH + h) * HD;     // d-row base (x TT elems)

    const int lrow = lane & 15, half = lane >> 4;
    const int g = lane >> 2, qc = lane & 3;
    const int rl0 = w * 16 + g, rl1 = rl0 + 8;            // local query rows

    // ---- stage Q tile into smem (KH/KL areas), pull frags to registers ----
    for (int idx = tid; idx < 128 * 8; idx += 256) {
        const int r = idx >> 3, c = idx & 7;
        const size_t gq = (qkbase + i0 + r) * HD + c * 8;
        cp16(smb + SM_KH + r * KP + c * 16, Qh + gq);
        cp16(smb + SM_KL + r * KP + c * 16, Ql + gq);
    }
    cp_commit(); cp_wait<0>(); __syncthreads();

    uint32_t qfh[4][4], qfl[4][4];
    {
        const uint32_t aB = smb + (uint32_t)(w * 16 + lrow) * KP + half * 16;
#pragma unroll
        for (int kd = 0; kd < 4; kd++) {
            ldm_x4(qfh[kd][0], qfh[kd][1], qfh[kd][2], qfh[kd][3], aB + kd * 32);
            ldm_x4(qfl[kd][0], qfl[kd][1], qfl[kd][2], qfl[kd][3],
                   aB + SM_KL + kd * 32);
        }
    }
    __syncthreads();

    float of[8][4];
#pragma unroll
    for (int i = 0; i < 8; i++)
#pragma unroll
        for (int j = 0; j < 4; j++) of[i][j] = 0.f;
    float m0 = -1e30f, m1 = -1e30f, l0 = 0.f, l1 = 0.f;

#pragma unroll
    for (int cc = 0; cc < 3; cc++) {
        const int cm = (cc == 0) ? 1 : (cc == 1) ? 0 : 2;   // diag, left, right
        const int j0 = i0 + (cm - 1) * 128;
        if (j0 < 0 || j0 >= TT) continue;

        // ---- load K chunk + V chunk ----
        for (int idx = tid; idx < 128 * 8; idx += 256) {
            const int r = idx >> 3, c = idx & 7;
            const size_t gk = (qkbase + j0 + r) * HD + c * 8;
            cp16(smb + SM_KH + r * KP + c * 16, Kh + gk);
            cp16(smb + SM_KL + r * KP + c * 16, Kl + gk);
        }
        for (int idx = tid; idx < 64 * 16; idx += 256) {
            const int r = idx >> 4, c = idx & 15;
            const size_t gv = (vbase + r) * TT + j0 + c * 8;
            cp16(smb + SM_VH + r * VP + c * 16, Vth + gv);
            cp16(smb + SM_VL + r * VP + c * 16, Vtl + gv);
        }
        cp_commit(); cp_wait<0>(); __syncthreads();

        // ---- S = Q K^T (3-pass split) ----
        float sf[16][4];
#pragma unroll
        for (int i = 0; i < 16; i++)
#pragma unroll
            for (int j = 0; j < 4; j++) sf[i][j] = 0.f;

        const uint32_t bB = smb + (uint32_t)lrow * KP + half * 16;
#pragma unroll
        for (int kd = 0; kd < 4; kd++) {
#pragma unroll
            for (int nt16 = 0; nt16 < 8; nt16++) {
                uint32_t t0, t1, t2, t3;
                uint32_t bh0[2], bh1[2], bl0[2], bl1[2];
                ldm_x4(t0, t1, t2, t3, bB + nt16 * 16 * KP + kd * 32);
                bh0[0] = t0; bh0[1] = t2; bh1[0] = t1; bh1[1] = t3;
                ldm_x4(t0, t1, t2, t3, bB + SM_KL + nt16 * 16 * KP + kd * 32);
                bl0[0] = t0; bl0[1] = t2; bl1[0] = t1; bl1[1] = t3;
                mma_bf16(sf[2 * nt16],     qfh[kd], bh0);
                mma_bf16(sf[2 * nt16],     qfh[kd], bl0);
                mma_bf16(sf[2 * nt16],     qfl[kd], bh0);
                mma_bf16(sf[2 * nt16 + 1], qfh[kd], bh1);
                mma_bf16(sf[2 * nt16 + 1], qfh[kd], bl1);
                mma_bf16(sf[2 * nt16 + 1], qfl[kd], bh1);
            }
        }

        // ---- band mask ----
        if (cm == 0) {            // left chunk: need col >= rl+1
#pragma unroll
            for (int nt = 0; nt < 16; nt++) {
                const int col = nt * 8 + 2 * qc;
                if (col     <= rl0) sf[nt][0] = -1e30f;
                if (col + 1 <= rl0) sf[nt][1] = -1e30f;
                if (col     <= rl1) sf[nt][2] = -1e30f;
                if (col + 1 <= rl1) sf[nt][3] = -1e30f;
            }
        } else if (cm == 2) {     // right chunk: need col <= rl
#pragma unroll
            for (int nt = 0; nt < 16; nt++) {
                const int col = nt * 8 + 2 * qc;
                if (col     > rl0) sf[nt][0] = -1e30f;
                if (col + 1 > rl0) sf[nt][1] = -1e30f;
                if (col     > rl1) sf[nt][2] = -1e30f;
                if (col + 1 > rl1) sf[nt][3] = -1e30f;
            }
        }

        // ---- online softmax (rows r0, r1 per thread; quad reduction) ----
        float mx0 = -1e30f, mx1 = -1e30f;
#pragma unroll
        for (int nt = 0; nt < 16; nt++) {
            mx0 = fmaxf(mx0, fmaxf(sf[nt][0], sf[nt][1]));
            mx1 = fmaxf(mx1, fmaxf(sf[nt][2], sf[nt][3]));
        }
        mx0 = fmaxf(mx0, __shfl_xor_sync(0xffffffffu, mx0, 1));
        mx0 = fmaxf(mx0, __shfl_xor_sync(0xffffffffu, mx0, 2));
        mx1 = fmaxf(mx1, __shfl_xor_sync(0xffffffffu, mx1, 1));
        mx1 = fmaxf(mx1, __shfl_xor_sync(0xffffffffu, mx1, 2));
        const float mn0 = fmaxf(m0, mx0), mn1 = fmaxf(m1, mx1);
        const float a0 = __expf(m0 - mn0), a1 = __expf(m1 - mn1);
        m0 = mn0; m1 = mn1;
        float s0 = 0.f, s1 = 0.f;
#pragma unroll
        for (int nt = 0; nt < 16; nt++) {
            sf[nt][0] = __expf(sf[nt][0] - m0);
            sf[nt][1] = __expf(sf[nt][1] - m0);
            sf[nt][2] = __expf(sf[nt][2] - m1);
            sf[nt][3] = __expf(sf[nt][3] - m1);
            s0 += sf[nt][0] + sf[nt][1];
            s1 += sf[nt][2] + sf[nt][3];
        }
        s0 += __shfl_xor_sync(0xffffffffu, s0, 1);
        s0 += __shfl_xor_sync(0xffffffffu, s0, 2);
        s1 += __shfl_xor_sync(0xffffffffu, s1, 1);
        s1 += __shfl_xor_sync(0xffffffffu, s1, 2);
        l0 = l0 * a0 + s0;
        l1 = l1 * a1 + s1;
#pragma unroll
        for (int nt = 0; nt < 8; nt++) {
            of[nt][0] *= a0; of[nt][1] *= a0;
            of[nt][2] *= a1; of[nt][3] *= a1;
        }

        // ---- O += P V (3-pass split) ----
        const uint32_t vB = smb + SM_VH + (uint32_t)lrow * VP + half * 16;
#pragma unroll
        for (int kk = 0; kk < 8; kk++) {
            uint32_t ph[4], pl[4];
            packbf(sf[2 * kk][0],     sf[2 * kk][1],     ph[0], pl[0]);
            packbf(sf[2 * kk][2],     sf[2 * kk][3],     ph[1], pl[1]);
            packbf(sf[2 * kk + 1][0], sf[2 * kk + 1][1], ph[2], pl[2]);
            packbf(sf[2 * kk + 1][2], sf[2 * kk + 1][3], ph[3], pl[3]);
#pragma unroll
            for (int nv = 0; nv < 4; nv++) {
                uint32_t t0, t1, t2, t3;
                uint32_t vh0[2], vh1[2], vl0[2], vl1[2];
                ldm_x4(t0, t1, t2, t3, vB + nv * 16 * VP + kk * 32);
                vh0[0] = t0; vh0[1] = t2; vh1[0] = t1; vh1[1] = t3;
                ldm_x4(t0, t1, t2, t3,
                       vB + (SM_VL - SM_VH) + nv * 16 * VP + kk * 32);
                vl0[0] = t0; vl0[1] = t2; vl1[0] = t1; vl1[1] = t3;
                mma_bf16(of[2 * nv],     ph, vh0);
                mma_bf16(of[2 * nv],     ph, vl0);
                mma_bf16(of[2 * nv],     pl, vh0);
                mma_bf16(of[2 * nv + 1], ph, vh1);
                mma_bf16(of[2 * nv + 1], ph, vl1);
                mma_bf16(of[2 * nv + 1], pl, vh1);
            }
        }
        __syncthreads();   // before next chunk load overwrites smem
    }

    // ---- normalize, split, store ----
    const float i0f = 1.0f / l0, i1f = 1.0f / l1;
    const int tg0 = i0 + rl0, tg1 = i0 + rl1;
#pragma unroll
    for (int nt = 0; nt < 8; nt++) {
        const int col = h * HD + nt * 8 + 2 * qc;
        uint32_t hi, lo;
        packbf(of[nt][0] * i0f, of[nt][1] * i0f, hi, lo);
        *(uint32_t*)(ohi + (size_t)(nb * TT + tg0) * DD + col) = hi;
        *(uint32_t*)(olo + (size_t)(nb * TT + tg0) * DD + col) = lo;
        packbf(of[nt][2] * i1f, of[nt][3] * i1f, hi, lo);
        *(uint32_t*)(ohi + (size_t)(nb * TT + tg1) * DD + col) = hi;
        *(uint32_t*)(olo + (size_t)(nb * TT + tg1) * DD + col) = lo;
    }
}

// ---------------------------------------------------------------------------
extern "C" void kernel_launch(void* const* d_in, const int* in_sizes, int n_in,
                              void* d_out, int out_size)
{
    const float* x     = (const float*)d_in[0];
    const float* w_qkv = (const float*)d_in[1];
    const float* w_out = (const float*)d_in[2];
    const float* b_out = (const float*)d_in[3];
    float* out = (float*)d_out;

    float* qkv;  cudaGetSymbolAddress((void**)&qkv, g_qkv);
    __nv_bfloat16 *xhi, *xlo, *wqh, *wql, *woh, *wol, *ahi, *alo;
    __nv_bfloat16 *qh, *ql, *kh, *kl, *vth, *vtl;
    cudaGetSymbolAddress((void**)&xhi, g_xhi);
    cudaGetSymbolAddress((void**)&xlo, g_xlo);
    cudaGetSymbolAddress((void**)&wqh, g_wqkv_hi);
    cudaGetSymbolAddress((void**)&wql, g_wqkv_lo);
    cudaGetSymbolAddress((void**)&woh, g_wout_hi);
    cudaGetSymbolAddress((void**)&wol, g_wout_lo);
    cudaGetSymbolAddress((void**)&ahi, g_ahi);
    cudaGetSymbolAddress((void**)&alo, g_alo);
    cudaGetSymbolAddress((void**)&qh,  g_qh);
    cudaGetSymbolAddress((void**)&ql,  g_ql);
    cudaGetSymbolAddress((void**)&kh,  g_kh);
    cudaGetSymbolAddress((void**)&kl,  g_kl);
    cudaGetSymbolAddress((void**)&vth, g_vth);
    cudaGetSymbolAddress((void**)&vtl, g_vtl);

    cudaFuncSetAttribute(gemm_hmma,
                         cudaFuncAttributeMaxDynamicSharedMemorySize, GEMM_SMEM);
    cudaFuncSetAttribute(attn_mma,
                         cudaFuncAttributeMaxDynamicSharedMemorySize, ATTN_SMEM);

    // 1) split inputs / weights to bf16 hi/lo
    {
        int n4 = MR * DD / 4;
        split_kernel<<<(n4 + 255) / 256, 256>>>(
            (const float4*)x, (__nv_bfloat162*)xhi, (__nv_bfloat162*)xlo, n4);
        n4 = QC * DD / 4;
        split_kernel<<<(n4 + 255) / 256, 256>>>(
            (const float4*)w_qkv, (__nv_bfloat162*)wqh, (__nv_bfloat162*)wql, n4);
        n4 = DD * DD / 4;
        split_kernel<<<(n4 + 255) / 256, 256>>>(
            (const float4*)w_out, (__nv_bfloat162*)woh, (__nv_bfloat162*)wol, n4);
    }

    // 2) QKV projection (HMMA)
    {
        dim3 grid(QC / 128, MR / 128);
        gemm_hmma<<<grid, 256, GEMM_SMEM>>>(QC, DD, xhi, xlo, wqh, wql,
                                            nullptr, qkv);
    }

    // 3) prep: RoPE+split Q/K, transpose+split V
    {
        dim3 grid(TT / 64, HH, NB);
        rope_split_qk<<<grid, 256>>>(qkv, qh, ql, kh, kl);
        vtrans_split<<<grid, 256>>>(qkv, vth, vtl);
    }

    // 4) MMA flash attention (banded), writes ahi/alo
    {
        dim3 grid(TT / 128, HH, NB);
        attn_mma<<<grid, 256, ATTN_SMEM>>>(qh, ql, kh, kl, vth, vtl, ahi, alo);
    }

    // 5) output projection (HMMA) + bias
    {
        dim3 grid(DD / 128, MR / 128);
        gemm_hmma<<<grid, 256, GEMM_SMEM>>>(DD, DD, ahi, alo, woh, wol,
                                            b_out, out);
    }
}

// round 7
// speedup vs baseline: 3.1351x; 1.3312x over previous
#include <cuda_runtime.h>
#include <cuda_bf16.h>
#include <cuda_fp16.h>
#include <cstdint>

// Problem constants
#define NB   2
#define TT   2048
#define DD   1024
#define HH   16
#define HD   64
#define MR   (NB * TT)            // 4096
#define QC   (3 * DD)             // 3072
#define FREQ_C 0.4152410118609203f   // log2(10000)/32

// HMMA GEMM tiling (2-pass fp16: A single, B split hi/lo)
#define BK      32
#define ROWB    80                  // 32 fp16 = 64B + 16B pad
#define TILE_B  (128 * ROWB)        // 10240
#define STG3    (3 * TILE_B)        // 30720 per stage (A, Bh, Bl)
#define GEMM_SMEM (3 * STG3)        // 92160, 3-stage pipeline

// attention smem pitches (unchanged R6 winner)
#define KP   144
#define VP   272
#define SM_KH 0
#define SM_KL 18432
#define SM_VH 36864
#define SM_VL 54272
#define ATTN_SMEM 71680

// ------------------------------ scratch -----------------------------------
__device__ __align__(128) float g_qkv[(size_t)MR * QC];
__device__ __align__(128) __half g_xh [(size_t)MR * DD];
__device__ __align__(128) __half g_wqh[(size_t)QC * DD];
__device__ __align__(128) __half g_wql[(size_t)QC * DD];
__device__ __align__(128) __half g_woh[(size_t)DD * DD];
__device__ __align__(128) __half g_wol[(size_t)DD * DD];
__device__ __align__(128) __half g_ah [(size_t)MR * DD];
// rope'd / split attention operands, head-major (bf16, 3-pass attn)
__device__ __align__(128) __nv_bfloat16 g_qh[(size_t)NB * HH * TT * HD];
__device__ __align__(128) __nv_bfloat16 g_ql[(size_t)NB * HH * TT * HD];
__device__ __align__(128) __nv_bfloat16 g_kh[(size_t)NB * HH * TT * HD];
__device__ __align__(128) __nv_bfloat16 g_kl[(size_t)NB * HH * TT * HD];
__device__ __align__(128) __nv_bfloat16 g_vth[(size_t)NB * HH * HD * TT];
__device__ __align__(128) __nv_bfloat16 g_vtl[(size_t)NB * HH * HD * TT];

// --------------------------- asm helpers ----------------------------------
__device__ __forceinline__ uint32_t s2u(const void* p) {
    uint32_t a;
    asm("{ .reg .u64 t; cvta.to.shared.u64 t, %1; cvt.u32.u64 %0, t; }"
        : "=r"(a) : "l"(p));
    return a;
}
__device__ __forceinline__ void cp16(uint32_t dst, const void* src) {
    asm volatile("cp.async.cg.shared.global [%0], [%1], 16;"
                 :: "r"(dst), "l"(__cvta_generic_to_global(src)) : "memory");
}
__device__ __forceinline__ void cp_commit() {
    asm volatile("cp.async.commit_group;" ::: "memory");
}
template <int N>
__device__ __forceinline__ void cp_wait() {
    asm volatile("cp.async.wait_group %0;" :: "n"(N) : "memory");
}
__device__ __forceinline__ void ldm_x4(uint32_t& r0, uint32_t& r1,
                                       uint32_t& r2, uint32_t& r3, uint32_t a) {
    asm volatile("ldmatrix.sync.aligned.m8n8.x4.shared.b16 {%0,%1,%2,%3}, [%4];"
                 : "=r"(r0), "=r"(r1), "=r"(r2), "=r"(r3) : "r"(a));
}
__device__ __forceinline__ void mma_bf16(float* c, const uint32_t* a,
                                         const uint32_t* b) {
    asm volatile(
        "mma.sync.aligned.m16n8k16.row.col.f32.bf16.bf16.f32 "
        "{%0,%1,%2,%3}, {%4,%5,%6,%7}, {%8,%9}, {%0,%1,%2,%3};"
        : "+f"(c[0]), "+f"(c[1]), "+f"(c[2]), "+f"(c[3])
        : "r"(a[0]), "r"(a[1]), "r"(a[2]), "r"(a[3]), "r"(b[0]), "r"(b[1]));
}
__device__ __forceinline__ void mma_f16(float* c, const uint32_t* a,
                                        const uint32_t* b) {
    asm volatile(
        "mma.sync.aligned.m16n8k16.row.col.f32.f16.f16.f32 "
        "{%0,%1,%2,%3}, {%4,%5,%6,%7}, {%8,%9}, {%0,%1,%2,%3};"
        : "+f"(c[0]), "+f"(c[1]), "+f"(c[2]), "+f"(c[3])
        : "r"(a[0]), "r"(a[1]), "r"(a[2]), "r"(a[3]), "r"(b[0]), "r"(b[1]));
}
__device__ __forceinline__ void split1(float v, __nv_bfloat16& h, __nv_bfloat16& l) {
    h = __float2bfloat16(v);
    l = __float2bfloat16(v - __bfloat162float(h));
}
__device__ __forceinline__ void packbf(float a, float b, uint32_t& hi, uint32_t& lo) {
    __nv_bfloat162 h = __floats2bfloat162_rn(a, b);
    __nv_bfloat162 l = __floats2bfloat162_rn(a - __bfloat162float(h.x),
                                             b - __bfloat162float(h.y));
    hi = *reinterpret_cast<uint32_t*>(&h);
    lo = *reinterpret_cast<uint32_t*>(&l);
}

// ---------------------------------------------------------------------------
// fp32 -> fp16 convert (A operands)
// ---------------------------------------------------------------------------
__global__ __launch_bounds__(256) void conv_half(
    const float4* __restrict__ src, __half2* __restrict__ dst, int n4)
{
    int i = blockIdx.x * blockDim.x + threadIdx.x;
    if (i >= n4) return;
    float4 v = src[i];
    dst[2 * i]     = __floats2half2_rn(v.x, v.y);
    dst[2 * i + 1] = __floats2half2_rn(v.z, v.w);
}

// fp32 -> fp16 hi/lo split (B operands / weights)
__global__ __launch_bounds__(256) void split_half(
    const float4* __restrict__ src, __half2* __restrict__ hi,
    __half2* __restrict__ lo, int n4)
{
    int i = blockIdx.x * blockDim.x + threadIdx.x;
    if (i >= n4) return;
    float4 v = src[i];
    __half2 h0 = __floats2half2_rn(v.x, v.y);
    __half2 h1 = __floats2half2_rn(v.z, v.w);
    __half2 l0 = __floats2half2_rn(v.x - __half2float(__low2half(h0)),
                                   v.y - __half2float(__high2half(h0)));
    __half2 l1 = __floats2half2_rn(v.z - __half2float(__low2half(h1)),
                                   v.w - __half2float(__high2half(h1)));
    hi[2 * i] = h0;  hi[2 * i + 1] = h1;
    lo[2 * i] = l0;  lo[2 * i + 1] = l1;
}

// ---------------------------------------------------------------------------
// HMMA GEMM, 2-pass fp16: C[M,N] = A[M,K] @ (Bh+Bl)[N,K]^T (+bias).
// CTA 128x128, 8 warps (2M x 4N), warp tile 64x32, BK=32, 3-stage cp.async.
// ---------------------------------------------------------------------------
__global__ __launch_bounds__(256) void gemm_hmma(
    int Ng, int Kg,
    const __half* __restrict__ A,
    const __half* __restrict__ Bh, const __half* __restrict__ Bl,
    const float* __restrict__ bias, float* __restrict__ C)
{
    extern __shared__ char sm[];
    const uint32_t smb = s2u(sm);

    const int tid  = threadIdx.x;
    const int lane = tid & 31;
    const int wid  = tid >> 5;
    const int wm   = wid & 1;
    const int wn   = wid >> 1;
    const int m0   = blockIdx.y * 128;
    const int n0   = blockIdx.x * 128;

    const int r0 = tid >> 2, c0 = (tid & 3);
    const int r1 = (tid + 256) >> 2, c1 = ((tid + 256) & 3);

    auto load_stage = [&](int st, int k0) {
        const uint32_t d0 = smb + st * STG3 + (uint32_t)r0 * ROWB + c0 * 16;
        const uint32_t d1 = smb + st * STG3 + (uint32_t)r1 * ROWB + c1 * 16;
        const size_t ga0 = (size_t)(m0 + r0) * Kg + k0 + c0 * 8;
        const size_t ga1 = (size_t)(m0 + r1) * Kg + k0 + c1 * 8;
        const size_t gb0 = (size_t)(n0 + r0) * Kg + k0 + c0 * 8;
        const size_t gb1 = (size_t)(n0 + r1) * Kg + k0 + c1 * 8;
        cp16(d0,              A  + ga0);  cp16(d1,              A  + ga1);
        cp16(d0 + TILE_B,     Bh + gb0);  cp16(d1 + TILE_B,     Bh + gb1);
        cp16(d0 + 2 * TILE_B, Bl + gb0);  cp16(d1 + 2 * TILE_B, Bl + gb1);
    };

    float acc[4][4][4];
#pragma unroll
    for (int i = 0; i < 4; i++)
#pragma unroll
        for (int j = 0; j < 4; j++)
#pragma unroll
            for (int k = 0; k < 4; k++) acc[i][j][k] = 0.f;

    load_stage(0, 0);  cp_commit();
    load_stage(1, BK); cp_commit();

    const int S = Kg / BK;
    const int lrow = lane & 15, lhalf = lane >> 4;

    for (int s = 0; s < S; s++) {
        if (s + 1 < S) cp_wait<1>(); else cp_wait<0>();
        __syncthreads();
        if (s + 2 < S) {
            int st = s + 2;  st -= (st >= 3) ? ((st / 3) * 3) : 0;
            load_stage((s + 2) % 3, (s + 2) * BK);
            cp_commit();
        }

        const uint32_t stb = smb + (s % 3) * STG3;
        const uint32_t aB = stb + (uint32_t)(wm * 64 + lrow) * ROWB + lhalf * 16;
        const uint32_t bB = stb + TILE_B +
                            (uint32_t)(wn * 32 + lrow) * ROWB + lhalf * 16;
#pragma unroll
        for (int k16 = 0; k16 < 2; k16++) {
            const uint32_t ko = k16 * 32;
            uint32_t a[4][4], bh[4][2], bl[4][2];
#pragma unroll
            for (int mt = 0; mt < 4; mt++)
                ldm_x4(a[mt][0], a[mt][1], a[mt][2], a[mt][3],
                       aB + ko + mt * 16 * ROWB);
#pragma unroll
            for (int bt = 0; bt < 2; bt++) {
                uint32_t t0, t1, t2, t3;
                ldm_x4(t0, t1, t2, t3, bB + ko + bt * 16 * ROWB);
                bh[bt * 2][0] = t0;  bh[bt * 2][1] = t2;
                bh[bt * 2 + 1][0] = t1;  bh[bt * 2 + 1][1] = t3;
                ldm_x4(t0, t1, t2, t3, bB + ko + bt * 16 * ROWB + TILE_B);
                bl[bt * 2][0] = t0;  bl[bt * 2][1] = t2;
                bl[bt * 2 + 1][0] = t1;  bl[bt * 2 + 1][1] = t3;
            }
#pragma unroll
            for (int mt = 0; mt < 4; mt++)
#pragma unroll
                for (int nt = 0; nt < 4; nt++) {
                    mma_f16(acc[mt][nt], a[mt], bh[nt]);
                    mma_f16(acc[mt][nt], a[mt], bl[nt]);
                }
        }
        __syncthreads();
    }

    const int erow = lane >> 2, ecol = (lane & 3) * 2;
#pragma unroll
    for (int mt = 0; mt < 4; mt++) {
        const int gr = m0 + wm * 64 + mt * 16 + erow;
#pragma unroll
        for (int nt = 0; nt < 4; nt++) {
            const int gc = n0 + wn * 32 + nt * 8 + ecol;
            float b0 = 0.f, b1 = 0.f;
            if (bias) { b0 = bias[gc]; b1 = bias[gc + 1]; }
            float2 v0 = {acc[mt][nt][0] + b0, acc[mt][nt][1] + b1};
            float2 v1 = {acc[mt][nt][2] + b0, acc[mt][nt][3] + b1};
            *(float2*)(C + (size_t)gr * Ng + gc)       = v0;
            *(float2*)(C + (size_t)(gr + 8) * Ng + gc) = v1;
        }
    }
}

// ---------------------------------------------------------------------------
// prep 1: RoPE + scale(Q) + split -> head-major Qh/Ql/Kh/Kl [nb][h][t][64]
// ---------------------------------------------------------------------------
__global__ __launch_bounds__(256) void rope_split_qk(
    const float* __restrict__ qkv,
    __nv_bfloat16* __restrict__ Qh, __nv_bfloat16* __restrict__ Ql,
    __nv_bfloat16* __restrict__ Kh, __nv_bfloat16* __restrict__ Kl)
{
    const int t0 = blockIdx.x * 64, h = blockIdx.y, nb = blockIdx.z;
    for (int idx = threadIdx.x; idx < 64 * 32; idx += 256) {
        const int tl = idx >> 5, p = idx & 31;
        const int t = t0 + tl;
        const float inv = exp2f(-(float)p * FREQ_C);
        float s, c;
        sincosf((float)t * inv, &s, &c);

        const size_t src = (size_t)(nb * TT + t) * QC + h * HD;
        const size_t dst = ((size_t)(nb * HH + h) * TT + t) * HD;

        const float q1 = qkv[src + p], q2 = qkv[src + p + 32];
        const float qa = (q1 * c - q2 * s) * 0.125f;
        const float qb = (q2 * c + q1 * s) * 0.125f;
        __nv_bfloat16 hh, ll;
        split1(qa, hh, ll);  Qh[dst + p] = hh;       Ql[dst + p] = ll;
        split1(qb, hh, ll);  Qh[dst + p + 32] = hh;  Ql[dst + p + 32] = ll;

        const float k1 = qkv[src + DD + p], k2 = qkv[src + DD + p + 32];
        const float ka = k1 * c - k2 * s;
        const float kb = k2 * c + k1 * s;
        split1(ka, hh, ll);  Kh[dst + p] = hh;       Kl[dst + p] = ll;
        split1(kb, hh, ll);  Kh[dst + p + 32] = hh;  Kl[dst + p + 32] = ll;
    }
}

// ---------------------------------------------------------------------------
// prep 2: V transpose + split -> Vt [nb][h][d][t]
// ---------------------------------------------------------------------------
__global__ __launch_bounds__(256) void vtrans_split(
    const float* __restrict__ qkv,
    __nv_bfloat16* __restrict__ Vth, __nv_bfloat16* __restrict__ Vtl)
{
    __shared__ float tile[64 * 65];
    const int t0 = blockIdx.x * 64, h = blockIdx.y, nb = blockIdx.z;
    for (int idx = threadIdx.x; idx < 64 * 64; idx += 256) {
        const int tl = idx >> 6, d = idx & 63;
        tile[tl * 65 + d] =
            qkv[(size_t)(nb * TT + t0 + tl) * QC + 2 * DD + h * HD + d];
    }
    __syncthreads();
    for (int idx = threadIdx.x; idx < 64 * 64; idx += 256) {
        const int d = idx >> 6, tl = idx & 63;
        const float v = tile[tl * 65 + d];
        __nv_bfloat16 hh, ll;
        split1(v, hh, ll);
        const size_t dst = ((size_t)(nb * HH + h) * HD + d) * TT + t0 + tl;
        Vth[dst] = hh;  Vtl[dst] = ll;
    }
}

// ---------------------------------------------------------------------------
// MMA flash attention (R6 winner); epilogue now writes single fp16.
// ---------------------------------------------------------------------------
__global__ __launch_bounds__(256, 1) void attn_mma(
    const __nv_bfloat16* __restrict__ Qh, const __nv_bfloat16* __restrict__ Ql,
    const __nv_bfloat16* __restrict__ Kh, const __nv_bfloat16* __restrict__ Kl,
    const __nv_bfloat16* __restrict__ Vth, const __nv_bfloat16* __restrict__ Vtl,
    __half* __restrict__ oh)
{
    extern __shared__ char sm[];
    const uint32_t smb = s2u(sm);

    const int tid = threadIdx.x, lane = tid & 31, w = tid >> 5;
    const int i0 = blockIdx.x * 128, h = blockIdx.y, nb = blockIdx.z;
    const size_t qkbase = (size_t)(nb * HH + h) * TT;
    const size_t vbase  = (size_t)(nb * HH + h) * HD;

    const int lrow = lane & 15, half = lane >> 4;
    const int g = lane >> 2, qc = lane & 3;
    const int rl0 = w * 16 + g, rl1 = rl0 + 8;

    for (int idx = tid; idx < 128 * 8; idx += 256) {
        const int r = idx >> 3, c = idx & 7;
        const size_t gq = (qkbase + i0 + r) * HD + c * 8;
        cp16(smb + SM_KH + r * KP + c * 16, Qh + gq);
        cp16(smb + SM_KL + r * KP + c * 16, Ql + gq);
    }
    cp_commit(); cp_wait<0>(); __syncthreads();

    uint32_t qfh[4][4], qfl[4][4];
    {
        const uint32_t aB = smb + (uint32_t)(w * 16 + lrow) * KP + half * 16;
#pragma unroll
        for (int kd = 0; kd < 4; kd++) {
            ldm_x4(qfh[kd][0], qfh[kd][1], qfh[kd][2], qfh[kd][3], aB + kd * 32);
            ldm_x4(qfl[kd][0], qfl[kd][1], qfl[kd][2], qfl[kd][3],
                   aB + SM_KL + kd * 32);
        }
    }
    __syncthreads();

    float of[8][4];
#pragma unroll
    for (int i = 0; i < 8; i++)
#pragma unroll
        for (int j = 0; j < 4; j++) of[i][j] = 0.f;
    float m0 = -1e30f, m1 = -1e30f, l0 = 0.f, l1 = 0.f;

#pragma unroll
    for (int cc = 0; cc < 3; cc++) {
        const int cm = (cc == 0) ? 1 : (cc == 1) ? 0 : 2;
        const int j0 = i0 + (cm - 1) * 128;
        if (j0 < 0 || j0 >= TT) continue;

        for (int idx = tid; idx < 128 * 8; idx += 256) {
            const int r = idx >> 3, c = idx & 7;
            const size_t gk = (qkbase + j0 + r) * HD + c * 8;
            cp16(smb + SM_KH + r * KP + c * 16, Kh + gk);
            cp16(smb + SM_KL + r * KP + c * 16, Kl + gk);
        }
        for (int idx = tid; idx < 64 * 16; idx += 256) {
            const int r = idx >> 4, c = idx & 15;
            const size_t gv = (vbase + r) * TT + j0 + c * 8;
            cp16(smb + SM_VH + r * VP + c * 16, Vth + gv);
            cp16(smb + SM_VL + r * VP + c * 16, Vtl + gv);
        }
        cp_commit(); cp_wait<0>(); __syncthreads();

        float sf[16][4];
#pragma unroll
        for (int i = 0; i < 16; i++)
#pragma unroll
            for (int j = 0; j < 4; j++) sf[i][j] = 0.f;

        const uint32_t bB = smb + (uint32_t)lrow * KP + half * 16;
#pragma unroll
        for (int kd = 0; kd < 4; kd++) {
#pragma unroll
            for (int nt16 = 0; nt16 < 8; nt16++) {
                uint32_t t0, t1, t2, t3;
                uint32_t bh0[2], bh1[2], bl0[2], bl1[2];
                ldm_x4(t0, t1, t2, t3, bB + nt16 * 16 * KP + kd * 32);
                bh0[0] = t0; bh0[1] = t2; bh1[0] = t1; bh1[1] = t3;
                ldm_x4(t0, t1, t2, t3, bB + SM_KL + nt16 * 16 * KP + kd * 32);
                bl0[0] = t0; bl0[1] = t2; bl1[0] = t1; bl1[1] = t3;
                mma_bf16(sf[2 * nt16],     qfh[kd], bh0);
                mma_bf16(sf[2 * nt16],     qfh[kd], bl0);
                mma_bf16(sf[2 * nt16],     qfl[kd], bh0);
                mma_bf16(sf[2 * nt16 + 1], qfh[kd], bh1);
                mma_bf16(sf[2 * nt16 + 1], qfh[kd], bl1);
                mma_bf16(sf[2 * nt16 + 1], qfl[kd], bh1);
            }
        }

        if (cm == 0) {
#pragma unroll
            for (int nt = 0; nt < 16; nt++) {
                const int col = nt * 8 + 2 * qc;
                if (col     <= rl0) sf[nt][0] = -1e30f;
                if (col + 1 <= rl0) sf[nt][1] = -1e30f;
                if (col     <= rl1) sf[nt][2] = -1e30f;
                if (col + 1 <= rl1) sf[nt][3] = -1e30f;
            }
        } else if (cm == 2) {
#pragma unroll
            for (int nt = 0; nt < 16; nt++) {
                const int col = nt * 8 + 2 * qc;
                if (col     > rl0) sf[nt][0] = -1e30f;
                if (col + 1 > rl0) sf[nt][1] = -1e30f;
                if (col     > rl1) sf[nt][2] = -1e30f;
                if (col + 1 > rl1) sf[nt][3] = -1e30f;
            }
        }

        float mx0 = -1e30f, mx1 = -1e30f;
#pragma unroll
        for (int nt = 0; nt < 16; nt++) {
            mx0 = fmaxf(mx0, fmaxf(sf[nt][0], sf[nt][1]));
            mx1 = fmaxf(mx1, fmaxf(sf[nt][2], sf[nt][3]));
        }
        mx0 = fmaxf(mx0, __shfl_xor_sync(0xffffffffu, mx0, 1));
        mx0 = fmaxf(mx0, __shfl_xor_sync(0xffffffffu, mx0, 2));
        mx1 = fmaxf(mx1, __shfl_xor_sync(0xffffffffu, mx1, 1));
        mx1 = fmaxf(mx1, __shfl_xor_sync(0xffffffffu, mx1, 2));
        const float mn0 = fmaxf(m0, mx0), mn1 = fmaxf(m1, mx1);
        const float a0 = __expf(m0 - mn0), a1 = __expf(m1 - mn1);
        m0 = mn0; m1 = mn1;
        float s0 = 0.f, s1 = 0.f;
#pragma unroll
        for (int nt = 0; nt < 16; nt++) {
            sf[nt][0] = __expf(sf[nt][0] - m0);
            sf[nt][1] = __expf(sf[nt][1] - m0);
            sf[nt][2] = __expf(sf[nt][2] - m1);
            sf[nt][3] = __expf(sf[nt][3] - m1);
            s0 += sf[nt][0] + sf[nt][1];
            s1 += sf[nt][2] + sf[nt][3];
        }
        s0 += __shfl_xor_sync(0xffffffffu, s0, 1);
        s0 += __shfl_xor_sync(0xffffffffu, s0, 2);
        s1 += __shfl_xor_sync(0xffffffffu, s1, 1);
        s1 += __shfl_xor_sync(0xffffffffu, s1, 2);
        l0 = l0 * a0 + s0;
        l1 = l1 * a1 + s1;
#pragma unroll
        for (int nt = 0; nt < 8; nt++) {
            of[nt][0] *= a0; of[nt][1] *= a0;
            of[nt][2] *= a1; of[nt][3] *= a1;
        }

        const uint32_t vB = smb + SM_VH + (uint32_t)lrow * VP + half * 16;
#pragma unroll
        for (int kk = 0; kk < 8; kk++) {
            uint32_t ph[4], pl[4];
            packbf(sf[2 * kk][0],     sf[2 * kk][1],     ph[0], pl[0]);
            packbf(sf[2 * kk][2],     sf[2 * kk][3],     ph[1], pl[1]);
            packbf(sf[2 * kk + 1][0], sf[2 * kk + 1][1], ph[2], pl[2]);
            packbf(sf[2 * kk + 1][2], sf[2 * kk + 1][3], ph[3], pl[3]);
#pragma unroll
            for (int nv = 0; nv < 4; nv++) {
                uint32_t t0, t1, t2, t3;
                uint32_t vh0[2], vh1[2], vl0[2], vl1[2];
                ldm_x4(t0, t1, t2, t3, vB + nv * 16 * VP + kk * 32);
                vh0[0] = t0; vh0[1] = t2; vh1[0] = t1; vh1[1] = t3;
                ldm_x4(t0, t1, t2, t3,
                       vB + (SM_VL - SM_VH) + nv * 16 * VP + kk * 32);
                vl0[0] = t0; vl0[1] = t2; vl1[0] = t1; vl1[1] = t3;
                mma_bf16(of[2 * nv],     ph, vh0);
                mma_bf16(of[2 * nv],     ph, vl0);
                mma_bf16(of[2 * nv],     pl, vh0);
                mma_bf16(of[2 * nv + 1], ph, vh1);
                mma_bf16(of[2 * nv + 1], ph, vl1);
                mma_bf16(of[2 * nv + 1], pl, vh1);
            }
        }
        __syncthreads();
    }

    // ---- normalize, convert to fp16, store ----
    const float i0f = 1.0f / l0, i1f = 1.0f / l1;
    const int tg0 = i0 + rl0, tg1 = i0 + rl1;
#pragma unroll
    for (int nt = 0; nt < 8; nt++) {
        const int col = h * HD + nt * 8 + 2 * qc;
        __half2 h2 = __floats2half2_rn(of[nt][0] * i0f, of[nt][1] * i0f);
        *(uint32_t*)(oh + (size_t)(nb * TT + tg0) * DD + col) =
            *reinterpret_cast<uint32_t*>(&h2);
        h2 = __floats2half2_rn(of[nt][2] * i1f, of[nt][3] * i1f);
        *(uint32_t*)(oh + (size_t)(nb * TT + tg1) * DD + col) =
            *reinterpret_cast<uint32_t*>(&h2);
    }
}

// ---------------------------------------------------------------------------
extern "C" void kernel_launch(void* const* d_in, const int* in_sizes, int n_in,
                              void* d_out, int out_size)
{
    const float* x     = (const float*)d_in[0];
    const float* w_qkv = (const float*)d_in[1];
    const float* w_out = (const float*)d_in[2];
    const float* b_out = (const float*)d_in[3];
    float* out = (float*)d_out;

    float* qkv;  cudaGetSymbolAddress((void**)&qkv, g_qkv);
    __half *xh, *wqh, *wql, *woh, *wol, *ah;
    __nv_bfloat16 *qh, *ql, *kh, *kl, *vth, *vtl;
    cudaGetSymbolAddress((void**)&xh,  g_xh);
    cudaGetSymbolAddress((void**)&wqh, g_wqh);
    cudaGetSymbolAddress((void**)&wql, g_wql);
    cudaGetSymbolAddress((void**)&woh, g_woh);
    cudaGetSymbolAddress((void**)&wol, g_wol);
    cudaGetSymbolAddress((void**)&ah,  g_ah);
    cudaGetSymbolAddress((void**)&qh,  g_qh);
    cudaGetSymbolAddress((void**)&ql,  g_ql);
    cudaGetSymbolAddress((void**)&kh,  g_kh);
    cudaGetSymbolAddress((void**)&kl,  g_kl);
    cudaGetSymbolAddress((void**)&vth, g_vth);
    cudaGetSymbolAddress((void**)&vtl, g_vtl);

    cudaFuncSetAttribute(gemm_hmma,
                         cudaFuncAttributeMaxDynamicSharedMemorySize, GEMM_SMEM);
    cudaFuncSetAttribute(attn_mma,
                         cudaFuncAttributeMaxDynamicSharedMemorySize, ATTN_SMEM);

    // 1) convert x to fp16; split weights to fp16 hi/lo
    {
        int n4 = MR * DD / 4;
        conv_half<<<(n4 + 255) / 256, 256>>>((const float4*)x, (__half2*)xh, n4);
        n4 = QC * DD / 4;
        split_half<<<(n4 + 255) / 256, 256>>>(
            (const float4*)w_qkv, (__half2*)wqh, (__half2*)wql, n4);
        n4 = DD * DD / 4;
        split_half<<<(n4 + 255) / 256, 256>>>(
            (const float4*)w_out, (__half2*)woh, (__half2*)wol, n4);
    }

    // 2) QKV projection (2-pass fp16 HMMA)
    {
        dim3 grid(QC / 128, MR / 128);
        gemm_hmma<<<grid, 256, GEMM_SMEM>>>(QC, DD, xh, wqh, wql, nullptr, qkv);
    }

    // 3) prep: RoPE+split Q/K, transpose+split V (bf16)
    {
        dim3 grid(TT / 64, HH, NB);
        rope_split_qk<<<grid, 256>>>(qkv, qh, ql, kh, kl);
        vtrans_split<<<grid, 256>>>(qkv, vth, vtl);
    }

    // 4) MMA flash attention (banded), writes fp16 attn-out
    {
        dim3 grid(TT / 128, HH, NB);
        attn_mma<<<grid, 256, ATTN_SMEM>>>(qh, ql, kh, kl, vth, vtl, ah);
    }

    // 5) output projection (2-pass fp16 HMMA) + bias
    {
        dim3 grid(DD / 128, MR / 128);
        gemm_hmma<<<grid, 256, GEMM_SMEM>>>(DD, DD, ah, woh, wol, b_out, out);
    }
}

// round 8
// speedup vs baseline: 3.6134x; 1.1525x over previous
#include <cuda_runtime.h>
#include <cuda_bf16.h>
#include <cuda_fp16.h>
#include <cstdint>

// Problem constants
#define NB   2
#define TT   2048
#define DD   1024
#define HH   16
#define HD   64
#define MR   (NB * TT)            // 4096
#define QC   (3 * DD)             // 3072
#define FREQ_C 0.4152410118609203f   // log2(10000)/32

// HMMA GEMM tiling: BK=64, 2-stage, one barrier per stage
#define BK      64
#define GROWB   144                 // 64 fp16 = 128B + 16B pad
#define GTILE   (128 * GROWB)       // 18432 per operand tile
#define GSTG    (3 * GTILE)         // 55296 per stage (A, Bh, Bl)
#define GEMM_SMEM (2 * GSTG)        // 110592

// attention smem pitches (unchanged winner)
#define KP   144
#define VP   272
#define SM_KH 0
#define SM_KL 18432
#define SM_VH 36864
#define SM_VL 54272
#define ATTN_SMEM 71680

// ------------------------------ scratch -----------------------------------
__device__ __align__(128) float g_qkv[(size_t)MR * QC];
__device__ __align__(128) __half g_xh [(size_t)MR * DD];
__device__ __align__(128) __half g_wqh[(size_t)QC * DD];
__device__ __align__(128) __half g_wql[(size_t)QC * DD];
__device__ __align__(128) __half g_woh[(size_t)DD * DD];
__device__ __align__(128) __half g_ah [(size_t)MR * DD];
// rope'd / split attention operands, head-major (bf16, 3-pass attn)
__device__ __align__(128) __nv_bfloat16 g_qh[(size_t)NB * HH * TT * HD];
__device__ __align__(128) __nv_bfloat16 g_ql[(size_t)NB * HH * TT * HD];
__device__ __align__(128) __nv_bfloat16 g_kh[(size_t)NB * HH * TT * HD];
__device__ __align__(128) __nv_bfloat16 g_kl[(size_t)NB * HH * TT * HD];
__device__ __align__(128) __nv_bfloat16 g_vth[(size_t)NB * HH * HD * TT];
__device__ __align__(128) __nv_bfloat16 g_vtl[(size_t)NB * HH * HD * TT];

// --------------------------- asm helpers ----------------------------------
__device__ __forceinline__ uint32_t s2u(const void* p) {
    uint32_t a;
    asm("{ .reg .u64 t; cvta.to.shared.u64 t, %1; cvt.u32.u64 %0, t; }"
        : "=r"(a) : "l"(p));
    return a;
}
__device__ __forceinline__ void cp16(uint32_t dst, const void* src) {
    asm volatile("cp.async.cg.shared.global [%0], [%1], 16;"
                 :: "r"(dst), "l"(__cvta_generic_to_global(src)) : "memory");
}
__device__ __forceinline__ void cp_commit() {
    asm volatile("cp.async.commit_group;" ::: "memory");
}
template <int N>
__device__ __forceinline__ void cp_wait() {
    asm volatile("cp.async.wait_group %0;" :: "n"(N) : "memory");
}
__device__ __forceinline__ void ldm_x4(uint32_t& r0, uint32_t& r1,
                                       uint32_t& r2, uint32_t& r3, uint32_t a) {
    asm volatile("ldmatrix.sync.aligned.m8n8.x4.shared.b16 {%0,%1,%2,%3}, [%4];"
                 : "=r"(r0), "=r"(r1), "=r"(r2), "=r"(r3) : "r"(a));
}
__device__ __forceinline__ void mma_bf16(float* c, const uint32_t* a,
                                         const uint32_t* b) {
    asm volatile(
        "mma.sync.aligned.m16n8k16.row.col.f32.bf16.bf16.f32 "
        "{%0,%1,%2,%3}, {%4,%5,%6,%7}, {%8,%9}, {%0,%1,%2,%3};"
        : "+f"(c[0]), "+f"(c[1]), "+f"(c[2]), "+f"(c[3])
        : "r"(a[0]), "r"(a[1]), "r"(a[2]), "r"(a[3]), "r"(b[0]), "r"(b[1]));
}
__device__ __forceinline__ void mma_f16(float* c, const uint32_t* a,
                                        const uint32_t* b) {
    asm volatile(
        "mma.sync.aligned.m16n8k16.row.col.f32.f16.f16.f32 "
        "{%0,%1,%2,%3}, {%4,%5,%6,%7}, {%8,%9}, {%0,%1,%2,%3};"
        : "+f"(c[0]), "+f"(c[1]), "+f"(c[2]), "+f"(c[3])
        : "r"(a[0]), "r"(a[1]), "r"(a[2]), "r"(a[3]), "r"(b[0]), "r"(b[1]));
}
__device__ __forceinline__ void split1(float v, __nv_bfloat16& h, __nv_bfloat16& l) {
    h = __float2bfloat16(v);
    l = __float2bfloat16(v - __bfloat162float(h));
}
__device__ __forceinline__ void packbf(float a, float b, uint32_t& hi, uint32_t& lo) {
    __nv_bfloat162 h = __floats2bfloat162_rn(a, b);
    __nv_bfloat162 l = __floats2bfloat162_rn(a - __bfloat162float(h.x),
                                             b - __bfloat162float(h.y));
    hi = *reinterpret_cast<uint32_t*>(&h);
    lo = *reinterpret_cast<uint32_t*>(&l);
}

// ---------------------------------------------------------------------------
// fp32 -> fp16 convert (A operands, and out-proj weights)
// ---------------------------------------------------------------------------
__global__ __launch_bounds__(256) void conv_half(
    const float4* __restrict__ src, __half2* __restrict__ dst, int n4)
{
    int i = blockIdx.x * blockDim.x + threadIdx.x;
    if (i >= n4) return;
    float4 v = src[i];
    dst[2 * i]     = __floats2half2_rn(v.x, v.y);
    dst[2 * i + 1] = __floats2half2_rn(v.z, v.w);
}

// fp32 -> fp16 hi/lo split (QKV weights)
__global__ __launch_bounds__(256) void split_half(
    const float4* __restrict__ src, __half2* __restrict__ hi,
    __half2* __restrict__ lo, int n4)
{
    int i = blockIdx.x * blockDim.x + threadIdx.x;
    if (i >= n4) return;
    float4 v = src[i];
    __half2 h0 = __floats2half2_rn(v.x, v.y);
    __half2 h1 = __floats2half2_rn(v.z, v.w);
    __half2 l0 = __floats2half2_rn(v.x - __half2float(__low2half(h0)),
                                   v.y - __half2float(__high2half(h0)));
    __half2 l1 = __floats2half2_rn(v.z - __half2float(__low2half(h1)),
                                   v.w - __half2float(__high2half(h1)));
    hi[2 * i] = h0;  hi[2 * i + 1] = h1;
    lo[2 * i] = l0;  lo[2 * i + 1] = l1;
}

// ---------------------------------------------------------------------------
// HMMA GEMM: C[M,N] = A[M,K] @ B[N,K]^T (+bias).  PASSES=2: B = Bh + Bl.
// CTA 128x128, 8 warps (2M x 4N), warp tile 64x32, BK=64, 2-stage pipeline,
// ONE __syncthreads per K-stage.
// ---------------------------------------------------------------------------
template <int PASSES>
__global__ __launch_bounds__(256) void gemm_hmma(
    int Ng, int Kg,
    const __half* __restrict__ A,
    const __half* __restrict__ Bh, const __half* __restrict__ Bl,
    const float* __restrict__ bias, float* __restrict__ C)
{
    extern __shared__ char sm[];
    const uint32_t smb = s2u(sm);

    const int tid  = threadIdx.x;
    const int lane = tid & 31;
    const int wid  = tid >> 5;
    const int wm   = wid & 1;
    const int wn   = wid >> 1;
    const int m0   = blockIdx.y * 128;
    const int n0   = blockIdx.x * 128;

    // stage loader: per tile 1024 x 16B chunks; 4 per thread (r=idx>>3, c=idx&7)
    auto load_stage = [&](int st, int k0) {
        const uint32_t base = smb + st * GSTG;
#pragma unroll
        for (int j = 0; j < 4; j++) {
            const int idx = tid + j * 256;
            const int r = idx >> 3, c = idx & 7;
            const uint32_t d = base + (uint32_t)r * GROWB + c * 16;
            const size_t ga = (size_t)(m0 + r) * Kg + k0 + c * 8;
            const size_t gb = (size_t)(n0 + r) * Kg + k0 + c * 8;
            cp16(d, A + ga);
            cp16(d + GTILE, Bh + gb);
            if (PASSES == 2) cp16(d + 2 * GTILE, Bl + gb);
        }
    };

    float acc[4][4][4];
#pragma unroll
    for (int i = 0; i < 4; i++)
#pragma unroll
        for (int j = 0; j < 4; j++)
#pragma unroll
            for (int k = 0; k < 4; k++) acc[i][j][k] = 0.f;

    load_stage(0, 0);
    cp_commit();

    const int S = Kg / BK;
    const int lrow = lane & 15, lhalf = lane >> 4;

    for (int s = 0; s < S; s++) {
        cp_wait<0>();
        __syncthreads();
        if (s + 1 < S) { load_stage((s + 1) & 1, (s + 1) * BK); cp_commit(); }

        const uint32_t stb = smb + (s & 1) * GSTG;
        const uint32_t aB = stb + (uint32_t)(wm * 64 + lrow) * GROWB + lhalf * 16;
        const uint32_t bB = stb + GTILE +
                            (uint32_t)(wn * 32 + lrow) * GROWB + lhalf * 16;
#pragma unroll
        for (int kd = 0; kd < 4; kd++) {
            const uint32_t ko = kd * 32;
            uint32_t a[4][4], bh[4][2], bl[4][2];
#pragma unroll
            for (int mt = 0; mt < 4; mt++)
                ldm_x4(a[mt][0], a[mt][1], a[mt][2], a[mt][3],
                       aB + ko + mt * 16 * GROWB);
#pragma unroll
            for (int bt = 0; bt < 2; bt++) {
                uint32_t t0, t1, t2, t3;
                ldm_x4(t0, t1, t2, t3, bB + ko + bt * 16 * GROWB);
                bh[bt * 2][0] = t0;  bh[bt * 2][1] = t2;
                bh[bt * 2 + 1][0] = t1;  bh[bt * 2 + 1][1] = t3;
                if (PASSES == 2) {
                    ldm_x4(t0, t1, t2, t3, bB + ko + bt * 16 * GROWB + GTILE);
                    bl[bt * 2][0] = t0;  bl[bt * 2][1] = t2;
                    bl[bt * 2 + 1][0] = t1;  bl[bt * 2 + 1][1] = t3;
                }
            }
#pragma unroll
            for (int mt = 0; mt < 4; mt++)
#pragma unroll
                for (int nt = 0; nt < 4; nt++) {
                    mma_f16(acc[mt][nt], a[mt], bh[nt]);
                    if (PASSES == 2) mma_f16(acc[mt][nt], a[mt], bl[nt]);
                }
        }
    }

    const int erow = lane >> 2, ecol = (lane & 3) * 2;
#pragma unroll
    for (int mt = 0; mt < 4; mt++) {
        const int gr = m0 + wm * 64 + mt * 16 + erow;
#pragma unroll
        for (int nt = 0; nt < 4; nt++) {
            const int gc = n0 + wn * 32 + nt * 8 + ecol;
            float b0 = 0.f, b1 = 0.f;
            if (bias) { b0 = bias[gc]; b1 = bias[gc + 1]; }
            float2 v0 = {acc[mt][nt][0] + b0, acc[mt][nt][1] + b1};
            float2 v1 = {acc[mt][nt][2] + b0, acc[mt][nt][3] + b1};
            *(float2*)(C + (size_t)gr * Ng + gc)       = v0;
            *(float2*)(C + (size_t)(gr + 8) * Ng + gc) = v1;
        }
    }
}

// ---------------------------------------------------------------------------
// prep 1: RoPE + scale(Q) + split -> head-major Qh/Ql/Kh/Kl [nb][h][t][64]
// ---------------------------------------------------------------------------
__global__ __launch_bounds__(256) void rope_split_qk(
    const float* __restrict__ qkv,
    __nv_bfloat16* __restrict__ Qh, __nv_bfloat16* __restrict__ Ql,
    __nv_bfloat16* __restrict__ Kh, __nv_bfloat16* __restrict__ Kl)
{
    const int t0 = blockIdx.x * 64, h = blockIdx.y, nb = blockIdx.z;
    for (int idx = threadIdx.x; idx < 64 * 32; idx += 256) {
        const int tl = idx >> 5, p = idx & 31;
        const int t = t0 + tl;
        const float inv = exp2f(-(float)p * FREQ_C);
        float s, c;
        sincosf((float)t * inv, &s, &c);

        const size_t src = (size_t)(nb * TT + t) * QC + h * HD;
        const size_t dst = ((size_t)(nb * HH + h) * TT + t) * HD;

        const float q1 = qkv[src + p], q2 = qkv[src + p + 32];
        const float qa = (q1 * c - q2 * s) * 0.125f;
        const float qb = (q2 * c + q1 * s) * 0.125f;
        __nv_bfloat16 hh, ll;
        split1(qa, hh, ll);  Qh[dst + p] = hh;       Ql[dst + p] = ll;
        split1(qb, hh, ll);  Qh[dst + p + 32] = hh;  Ql[dst + p + 32] = ll;

        const float k1 = qkv[src + DD + p], k2 = qkv[src + DD + p + 32];
        const float ka = k1 * c - k2 * s;
        const float kb = k2 * c + k1 * s;
        split1(ka, hh, ll);  Kh[dst + p] = hh;       Kl[dst + p] = ll;
        split1(kb, hh, ll);  Kh[dst + p + 32] = hh;  Kl[dst + p + 32] = ll;
    }
}

// ---------------------------------------------------------------------------
// prep 2: V transpose + split -> Vt [nb][h][d][t]
// ---------------------------------------------------------------------------
__global__ __launch_bounds__(256) void vtrans_split(
    const float* __restrict__ qkv,
    __nv_bfloat16* __restrict__ Vth, __nv_bfloat16* __restrict__ Vtl)
{
    __shared__ float tile[64 * 65];
    const int t0 = blockIdx.x * 64, h = blockIdx.y, nb = blockIdx.z;
    for (int idx = threadIdx.x; idx < 64 * 64; idx += 256) {
        const int tl = idx >> 6, d = idx & 63;
        tile[tl * 65 + d] =
            qkv[(size_t)(nb * TT + t0 + tl) * QC + 2 * DD + h * HD + d];
    }
    __syncthreads();
    for (int idx = threadIdx.x; idx < 64 * 64; idx += 256) {
        const int d = idx >> 6, tl = idx & 63;
        const float v = tile[tl * 65 + d];
        __nv_bfloat16 hh, ll;
        split1(v, hh, ll);
        const size_t dst = ((size_t)(nb * HH + h) * HD + d) * TT + t0 + tl;
        Vth[dst] = hh;  Vtl[dst] = ll;
    }
}

// ---------------------------------------------------------------------------
// MMA flash attention (unchanged winner); epilogue writes single fp16.
// ---------------------------------------------------------------------------
__global__ __launch_bounds__(256, 1) void attn_mma(
    const __nv_bfloat16* __restrict__ Qh, const __nv_bfloat16* __restrict__ Ql,
    const __nv_bfloat16* __restrict__ Kh, const __nv_bfloat16* __restrict__ Kl,
    const __nv_bfloat16* __restrict__ Vth, const __nv_bfloat16* __restrict__ Vtl,
    __half* __restrict__ oh)
{
    extern __shared__ char sm[];
    const uint32_t smb = s2u(sm);

    const int tid = threadIdx.x, lane = tid & 31, w = tid >> 5;
    const int i0 = blockIdx.x * 128, h = blockIdx.y, nb = blockIdx.z;
    const size_t qkbase = (size_t)(nb * HH + h) * TT;
    const size_t vbase  = (size_t)(nb * HH + h) * HD;

    const int lrow = lane & 15, half = lane >> 4;
    const int g = lane >> 2, qc = lane & 3;
    const int rl0 = w * 16 + g, rl1 = rl0 + 8;

    for (int idx = tid; idx < 128 * 8; idx += 256) {
        const int r = idx >> 3, c = idx & 7;
        const size_t gq = (qkbase + i0 + r) * HD + c * 8;
        cp16(smb + SM_KH + r * KP + c * 16, Qh + gq);
        cp16(smb + SM_KL + r * KP + c * 16, Ql + gq);
    }
    cp_commit(); cp_wait<0>(); __syncthreads();

    uint32_t qfh[4][4], qfl[4][4];
    {
        const uint32_t aB = smb + (uint32_t)(w * 16 + lrow) * KP + half * 16;
#pragma unroll
        for (int kd = 0; kd < 4; kd++) {
            ldm_x4(qfh[kd][0], qfh[kd][1], qfh[kd][2], qfh[kd][3], aB + kd * 32);
            ldm_x4(qfl[kd][0], qfl[kd][1], qfl[kd][2], qfl[kd][3],
                   aB + SM_KL + kd * 32);
        }
    }
    __syncthreads();

    float of[8][4];
#pragma unroll
    for (int i = 0; i < 8; i++)
#pragma unroll
        for (int j = 0; j < 4; j++) of[i][j] = 0.f;
    float m0 = -1e30f, m1 = -1e30f, l0 = 0.f, l1 = 0.f;

#pragma unroll
    for (int cc = 0; cc < 3; cc++) {
        const int cm = (cc == 0) ? 1 : (cc == 1) ? 0 : 2;
        const int j0 = i0 + (cm - 1) * 128;
        if (j0 < 0 || j0 >= TT) continue;

        for (int idx = tid; idx < 128 * 8; idx += 256) {
            const int r = idx >> 3, c = idx & 7;
            const size_t gk = (qkbase + j0 + r) * HD + c * 8;
            cp16(smb + SM_KH + r * KP + c * 16, Kh + gk);
            cp16(smb + SM_KL + r * KP + c * 16, Kl + gk);
        }
        for (int idx = tid; idx < 64 * 16; idx += 256) {
            const int r = idx >> 4, c = idx & 15;
            const size_t gv = (vbase + r) * TT + j0 + c * 8;
            cp16(smb + SM_VH + r * VP + c * 16, Vth + gv);
            cp16(smb + SM_VL + r * VP + c * 16, Vtl + gv);
        }
        cp_commit(); cp_wait<0>(); __syncthreads();

        float sf[16][4];
#pragma unroll
        for (int i = 0; i < 16; i++)
#pragma unroll
            for (int j = 0; j < 4; j++) sf[i][j] = 0.f;

        const uint32_t bB = smb + (uint32_t)lrow * KP + half * 16;
#pragma unroll
        for (int kd = 0; kd < 4; kd++) {
#pragma unroll
            for (int nt16 = 0; nt16 < 8; nt16++) {
                uint32_t t0, t1, t2, t3;
                uint32_t bh0[2], bh1[2], bl0[2], bl1[2];
                ldm_x4(t0, t1, t2, t3, bB + nt16 * 16 * KP + kd * 32);
                bh0[0] = t0; bh0[1] = t2; bh1[0] = t1; bh1[1] = t3;
                ldm_x4(t0, t1, t2, t3, bB + SM_KL + nt16 * 16 * KP + kd * 32);
                bl0[0] = t0; bl0[1] = t2; bl1[0] = t1; bl1[1] = t3;
                mma_bf16(sf[2 * nt16],     qfh[kd], bh0);
                mma_bf16(sf[2 * nt16],     qfh[kd], bl0);
                mma_bf16(sf[2 * nt16],     qfl[kd], bh0);
                mma_bf16(sf[2 * nt16 + 1], qfh[kd], bh1);
                mma_bf16(sf[2 * nt16 + 1], qfh[kd], bl1);
                mma_bf16(sf[2 * nt16 + 1], qfl[kd], bh1);
            }
        }

        if (cm == 0) {
#pragma unroll
            for (int nt = 0; nt < 16; nt++) {
                const int col = nt * 8 + 2 * qc;
                if (col     <= rl0) sf[nt][0] = -1e30f;
                if (col + 1 <= rl0) sf[nt][1] = -1e30f;
                if (col     <= rl1) sf[nt][2] = -1e30f;
                if (col + 1 <= rl1) sf[nt][3] = -1e30f;
            }
        } else if (cm == 2) {
#pragma unroll
            for (int nt = 0; nt < 16; nt++) {
                const int col = nt * 8 + 2 * qc;
                if (col     > rl0) sf[nt][0] = -1e30f;
                if (col + 1 > rl0) sf[nt][1] = -1e30f;
                if (col     > rl1) sf[nt][2] = -1e30f;
                if (col + 1 > rl1) sf[nt][3] = -1e30f;
            }
        }

        float mx0 = -1e30f, mx1 = -1e30f;
#pragma unroll
        for (int nt = 0; nt < 16; nt++) {
            mx0 = fmaxf(mx0, fmaxf(sf[nt][0], sf[nt][1]));
            mx1 = fmaxf(mx1, fmaxf(sf[nt][2], sf[nt][3]));
        }
        mx0 = fmaxf(mx0, __shfl_xor_sync(0xffffffffu, mx0, 1));
        mx0 = fmaxf(mx0, __shfl_xor_sync(0xffffffffu, mx0, 2));
        mx1 = fmaxf(mx1, __shfl_xor_sync(0xffffffffu, mx1, 1));
        mx1 = fmaxf(mx1, __shfl_xor_sync(0xffffffffu, mx1, 2));
        const float mn0 = fmaxf(m0, mx0), mn1 = fmaxf(m1, mx1);
        const float a0 = __expf(m0 - mn0), a1 = __expf(m1 - mn1);
        m0 = mn0; m1 = mn1;
        float s0 = 0.f, s1 = 0.f;
#pragma unroll
        for (int nt = 0; nt < 16; nt++) {
            sf[nt][0] = __expf(sf[nt][0] - m0);
            sf[nt][1] = __expf(sf[nt][1] - m0);
            sf[nt][2] = __expf(sf[nt][2] - m1);
            sf[nt][3] = __expf(sf[nt][3] - m1);
            s0 += sf[nt][0] + sf[nt][1];
            s1 += sf[nt][2] + sf[nt][3];
        }
        s0 += __shfl_xor_sync(0xffffffffu, s0, 1);
        s0 += __shfl_xor_sync(0xffffffffu, s0, 2);
        s1 += __shfl_xor_sync(0xffffffffu, s1, 1);
        s1 += __shfl_xor_sync(0xffffffffu, s1, 2);
        l0 = l0 * a0 + s0;
        l1 = l1 * a1 + s1;
#pragma unroll
        for (int nt = 0; nt < 8; nt++) {
            of[nt][0] *= a0; of[nt][1] *= a0;
            of[nt][2] *= a1; of[nt][3] *= a1;
        }

        const uint32_t vB = smb + SM_VH + (uint32_t)lrow * VP + half * 16;
#pragma unroll
        for (int kk = 0; kk < 8; kk++) {
            uint32_t ph[4], pl[4];
            packbf(sf[2 * kk][0],     sf[2 * kk][1],     ph[0], pl[0]);
            packbf(sf[2 * kk][2],     sf[2 * kk][3],     ph[1], pl[1]);
            packbf(sf[2 * kk + 1][0], sf[2 * kk + 1][1], ph[2], pl[2]);
            packbf(sf[2 * kk + 1][2], sf[2 * kk + 1][3], ph[3], pl[3]);
#pragma unroll
            for (int nv = 0; nv < 4; nv++) {
                uint32_t t0, t1, t2, t3;
                uint32_t vh0[2], vh1[2], vl0[2], vl1[2];
                ldm_x4(t0, t1, t2, t3, vB + nv * 16 * VP + kk * 32);
                vh0[0] = t0; vh0[1] = t2; vh1[0] = t1; vh1[1] = t3;
                ldm_x4(t0, t1, t2, t3,
                       vB + (SM_VL - SM_VH) + nv * 16 * VP + kk * 32);
                vl0[0] = t0; vl0[1] = t2; vl1[0] = t1; vl1[1] = t3;
                mma_bf16(of[2 * nv],     ph, vh0);
                mma_bf16(of[2 * nv],     ph, vl0);
                mma_bf16(of[2 * nv],     pl, vh0);
                mma_bf16(of[2 * nv + 1], ph, vh1);
                mma_bf16(of[2 * nv + 1], ph, vl1);
                mma_bf16(of[2 * nv + 1], pl, vh1);
            }
        }
        __syncthreads();
    }

    const float i0f = 1.0f / l0, i1f = 1.0f / l1;
    const int tg0 = i0 + rl0, tg1 = i0 + rl1;
#pragma unroll
    for (int nt = 0; nt < 8; nt++) {
        const int col = h * HD + nt * 8 + 2 * qc;
        __half2 h2 = __floats2half2_rn(of[nt][0] * i0f, of[nt][1] * i0f);
        *(uint32_t*)(oh + (size_t)(nb * TT + tg0) * DD + col) =
            *reinterpret_cast<uint32_t*>(&h2);
        h2 = __floats2half2_rn(of[nt][2] * i1f, of[nt][3] * i1f);
        *(uint32_t*)(oh + (size_t)(nb * TT + tg1) * DD + col) =
            *reinterpret_cast<uint32_t*>(&h2);
    }
}

// ---------------------------------------------------------------------------
extern "C" void kernel_launch(void* const* d_in, const int* in_sizes, int n_in,
                              void* d_out, int out_size)
{
    const float* x     = (const float*)d_in[0];
    const float* w_qkv = (const float*)d_in[1];
    const float* w_out = (const float*)d_in[2];
    const float* b_out = (const float*)d_in[3];
    float* out = (float*)d_out;

    float* qkv;  cudaGetSymbolAddress((void**)&qkv, g_qkv);
    __half *xh, *wqh, *wql, *woh, *ah;
    __nv_bfloat16 *qh, *ql, *kh, *kl, *vth, *vtl;
    cudaGetSymbolAddress((void**)&xh,  g_xh);
    cudaGetSymbolAddress((void**)&wqh, g_wqh);
    cudaGetSymbolAddress((void**)&wql, g_wql);
    cudaGetSymbolAddress((void**)&woh, g_woh);
    cudaGetSymbolAddress((void**)&ah,  g_ah);
    cudaGetSymbolAddress((void**)&qh,  g_qh);
    cudaGetSymbolAddress((void**)&ql,  g_ql);
    cudaGetSymbolAddress((void**)&kh,  g_kh);
    cudaGetSymbolAddress((void**)&kl,  g_kl);
    cudaGetSymbolAddress((void**)&vth, g_vth);
    cudaGetSymbolAddress((void**)&vtl, g_vtl);

    cudaFuncSetAttribute(gemm_hmma<2>,
                         cudaFuncAttributeMaxDynamicSharedMemorySize, GEMM_SMEM);
    cudaFuncSetAttribute(gemm_hmma<1>,
                         cudaFuncAttributeMaxDynamicSharedMemorySize, GEMM_SMEM);
    cudaFuncSetAttribute(attn_mma,
                         cudaFuncAttributeMaxDynamicSharedMemorySize, ATTN_SMEM);

    // 1) convert x & w_out to fp16; split w_qkv to fp16 hi/lo
    {
        int n4 = MR * DD / 4;
        conv_half<<<(n4 + 255) / 256, 256>>>((const float4*)x, (__half2*)xh, n4);
        n4 = QC * DD / 4;
        split_half<<<(n4 + 255) / 256, 256>>>(
            (const float4*)w_qkv, (__half2*)wqh, (__half2*)wql, n4);
        n4 = DD * DD / 4;
        conv_half<<<(n4 + 255) / 256, 256>>>(
            (const float4*)w_out, (__half2*)woh, n4);
    }

    // 2) QKV projection (2-pass fp16 HMMA)
    {
        dim3 grid(QC / 128, MR / 128);
        gemm_hmma<2><<<grid, 256, GEMM_SMEM>>>(QC, DD, xh, wqh, wql,
                                               nullptr, qkv);
    }

    // 3) prep: RoPE+split Q/K, transpose+split V (bf16)
    {
        dim3 grid(TT / 64, HH, NB);
        rope_split_qk<<<grid, 256>>>(qkv, qh, ql, kh, kl);
        vtrans_split<<<grid, 256>>>(qkv, vth, vtl);
    }

    // 4) MMA flash attention (banded), writes fp16 attn-out
    {
        dim3 grid(TT / 128, HH, NB);
        attn_mma<<<grid, 256, ATTN_SMEM>>>(qh, ql, kh, kl, vth, vtl, ah);
    }

    // 5) output projection (1-pass fp16 HMMA) + bias
    {
        dim3 grid(DD / 128, MR / 128);
        gemm_hmma<1><<<grid, 256, GEMM_SMEM>>>(DD, DD, ah, woh, nullptr,
                                               b_out, out);
    }
}

// round 9
// speedup vs baseline: 4.6423x; 1.2847x over previous
#include <cuda_runtime.h>
#include <cuda_bf16.h>
#include <cuda_fp16.h>
#include <cstdint>

// Problem constants
#define NB   2
#define TT   2048
#define DD   1024
#define HH   16
#define HD   64
#define MR   (NB * TT)            // 4096
#define QC   (3 * DD)             // 3072
#define FREQ_C 0.4152410118609203f   // log2(10000)/32

// HMMA GEMM tiling: BK=64, 2-stage, one barrier per stage, 1-pass fp16
#define BK      64
#define GROWB   144                 // 64 fp16 = 128B + 16B pad
#define GTILE   (128 * GROWB)       // 18432 per operand tile
#define GSTG    (2 * GTILE)         // 36864 per stage (A, B)
#define GEMM_SMEM (2 * GSTG)        // 73728

// attention smem pitches (unchanged winner)
#define KP   144
#define VP   272
#define SM_KH 0
#define SM_KL 18432
#define SM_VH 36864
#define SM_VL 54272
#define ATTN_SMEM 71680

// ------------------------------ scratch -----------------------------------
__device__ __align__(128) float g_qkv[(size_t)MR * QC];
__device__ __align__(128) __half g_xh [(size_t)MR * DD];
__device__ __align__(128) __half g_wqh[(size_t)QC * DD];
__device__ __align__(128) __half g_woh[(size_t)DD * DD];
__device__ __align__(128) __half g_ah [(size_t)MR * DD];
// rope'd / split attention operands, head-major (bf16, 3-pass attn)
__device__ __align__(128) __nv_bfloat16 g_qh[(size_t)NB * HH * TT * HD];
__device__ __align__(128) __nv_bfloat16 g_ql[(size_t)NB * HH * TT * HD];
__device__ __align__(128) __nv_bfloat16 g_kh[(size_t)NB * HH * TT * HD];
__device__ __align__(128) __nv_bfloat16 g_kl[(size_t)NB * HH * TT * HD];
__device__ __align__(128) __nv_bfloat16 g_vth[(size_t)NB * HH * HD * TT];
__device__ __align__(128) __nv_bfloat16 g_vtl[(size_t)NB * HH * HD * TT];

// --------------------------- asm helpers ----------------------------------
__device__ __forceinline__ uint32_t s2u(const void* p) {
    uint32_t a;
    asm("{ .reg .u64 t; cvta.to.shared.u64 t, %1; cvt.u32.u64 %0, t; }"
        : "=r"(a) : "l"(p));
    return a;
}
__device__ __forceinline__ void cp16(uint32_t dst, const void* src) {
    asm volatile("cp.async.cg.shared.global [%0], [%1], 16;"
                 :: "r"(dst), "l"(__cvta_generic_to_global(src)) : "memory");
}
__device__ __forceinline__ void cp_commit() {
    asm volatile("cp.async.commit_group;" ::: "memory");
}
template <int N>
__device__ __forceinline__ void cp_wait() {
    asm volatile("cp.async.wait_group %0;" :: "n"(N) : "memory");
}
__device__ __forceinline__ void ldm_x4(uint32_t& r0, uint32_t& r1,
                                       uint32_t& r2, uint32_t& r3, uint32_t a) {
    asm volatile("ldmatrix.sync.aligned.m8n8.x4.shared.b16 {%0,%1,%2,%3}, [%4];"
                 : "=r"(r0), "=r"(r1), "=r"(r2), "=r"(r3) : "r"(a));
}
__device__ __forceinline__ void mma_bf16(float* c, const uint32_t* a,
                                         const uint32_t* b) {
    asm volatile(
        "mma.sync.aligned.m16n8k16.row.col.f32.bf16.bf16.f32 "
        "{%0,%1,%2,%3}, {%4,%5,%6,%7}, {%8,%9}, {%0,%1,%2,%3};"
        : "+f"(c[0]), "+f"(c[1]), "+f"(c[2]), "+f"(c[3])
        : "r"(a[0]), "r"(a[1]), "r"(a[2]), "r"(a[3]), "r"(b[0]), "r"(b[1]));
}
__device__ __forceinline__ void mma_f16(float* c, const uint32_t* a,
                                        const uint32_t* b) {
    asm volatile(
        "mma.sync.aligned.m16n8k16.row.col.f32.f16.f16.f32 "
        "{%0,%1,%2,%3}, {%4,%5,%6,%7}, {%8,%9}, {%0,%1,%2,%3};"
        : "+f"(c[0]), "+f"(c[1]), "+f"(c[2]), "+f"(c[3])
        : "r"(a[0]), "r"(a[1]), "r"(a[2]), "r"(a[3]), "r"(b[0]), "r"(b[1]));
}
__device__ __forceinline__ void split1(float v, __nv_bfloat16& h, __nv_bfloat16& l) {
    h = __float2bfloat16(v);
    l = __float2bfloat16(v - __bfloat162float(h));
}
__device__ __forceinline__ void packbf(float a, float b, uint32_t& hi, uint32_t& lo) {
    __nv_bfloat162 h = __floats2bfloat162_rn(a, b);
    __nv_bfloat162 l = __floats2bfloat162_rn(a - __bfloat162float(h.x),
                                             b - __bfloat162float(h.y));
    hi = *reinterpret_cast<uint32_t*>(&h);
    lo = *reinterpret_cast<uint32_t*>(&l);
}

// ---------------------------------------------------------------------------
// fp32 -> fp16 convert
// ---------------------------------------------------------------------------
__global__ __launch_bounds__(256) void conv_half(
    const float4* __restrict__ src, __half2* __restrict__ dst, int n4)
{
    int i = blockIdx.x * blockDim.x + threadIdx.x;
    if (i >= n4) return;
    float4 v = src[i];
    dst[2 * i]     = __floats2half2_rn(v.x, v.y);
    dst[2 * i + 1] = __floats2half2_rn(v.z, v.w);
}

// ---------------------------------------------------------------------------
// HMMA GEMM, 1-pass fp16: C[M,N] = A[M,K] @ B[N,K]^T (+bias).
// CTA 128x128, 8 warps (2M x 4N), warp tile 64x32, BK=64, 2-stage pipeline,
// one __syncthreads per K-stage.
// ---------------------------------------------------------------------------
__global__ __launch_bounds__(256) void gemm_hmma(
    int Ng, int Kg,
    const __half* __restrict__ A, const __half* __restrict__ B,
    const float* __restrict__ bias, float* __restrict__ C)
{
    extern __shared__ char sm[];
    const uint32_t smb = s2u(sm);

    const int tid  = threadIdx.x;
    const int lane = tid & 31;
    const int wid  = tid >> 5;
    const int wm   = wid & 1;
    const int wn   = wid >> 1;
    const int m0   = blockIdx.y * 128;
    const int n0   = blockIdx.x * 128;

    auto load_stage = [&](int st, int k0) {
        const uint32_t base = smb + st * GSTG;
#pragma unroll
        for (int j = 0; j < 4; j++) {
            const int idx = tid + j * 256;
            const int r = idx >> 3, c = idx & 7;
            const uint32_t d = base + (uint32_t)r * GROWB + c * 16;
            cp16(d,         A + (size_t)(m0 + r) * Kg + k0 + c * 8);
            cp16(d + GTILE, B + (size_t)(n0 + r) * Kg + k0 + c * 8);
        }
    };

    float acc[4][4][4];
#pragma unroll
    for (int i = 0; i < 4; i++)
#pragma unroll
        for (int j = 0; j < 4; j++)
#pragma unroll
            for (int k = 0; k < 4; k++) acc[i][j][k] = 0.f;

    load_stage(0, 0);
    cp_commit();

    const int S = Kg / BK;
    const int lrow = lane & 15, lhalf = lane >> 4;

    for (int s = 0; s < S; s++) {
        cp_wait<0>();
        __syncthreads();
        if (s + 1 < S) { load_stage((s + 1) & 1, (s + 1) * BK); cp_commit(); }

        const uint32_t stb = smb + (s & 1) * GSTG;
        const uint32_t aB = stb + (uint32_t)(wm * 64 + lrow) * GROWB + lhalf * 16;
        const uint32_t bB = stb + GTILE +
                            (uint32_t)(wn * 32 + lrow) * GROWB + lhalf * 16;
#pragma unroll
        for (int kd = 0; kd < 4; kd++) {
            const uint32_t ko = kd * 32;
            uint32_t a[4][4], bh[4][2];
#pragma unroll
            for (int mt = 0; mt < 4; mt++)
                ldm_x4(a[mt][0], a[mt][1], a[mt][2], a[mt][3],
                       aB + ko + mt * 16 * GROWB);
#pragma unroll
            for (int bt = 0; bt < 2; bt++) {
                uint32_t t0, t1, t2, t3;
                ldm_x4(t0, t1, t2, t3, bB + ko + bt * 16 * GROWB);
                bh[bt * 2][0] = t0;  bh[bt * 2][1] = t2;
                bh[bt * 2 + 1][0] = t1;  bh[bt * 2 + 1][1] = t3;
            }
#pragma unroll
            for (int mt = 0; mt < 4; mt++)
#pragma unroll
                for (int nt = 0; nt < 4; nt++)
                    mma_f16(acc[mt][nt], a[mt], bh[nt]);
        }
    }

    const int erow = lane >> 2, ecol = (lane & 3) * 2;
#pragma unroll
    for (int mt = 0; mt < 4; mt++) {
        const int gr = m0 + wm * 64 + mt * 16 + erow;
#pragma unroll
        for (int nt = 0; nt < 4; nt++) {
            const int gc = n0 + wn * 32 + nt * 8 + ecol;
            float b0 = 0.f, b1 = 0.f;
            if (bias) { b0 = bias[gc]; b1 = bias[gc + 1]; }
            float2 v0 = {acc[mt][nt][0] + b0, acc[mt][nt][1] + b1};
            float2 v1 = {acc[mt][nt][2] + b0, acc[mt][nt][3] + b1};
            *(float2*)(C + (size_t)gr * Ng + gc)       = v0;
            *(float2*)(C + (size_t)(gr + 8) * Ng + gc) = v1;
        }
    }
}

// ---------------------------------------------------------------------------
// prep 1: RoPE + scale(Q) + split -> head-major Qh/Ql/Kh/Kl [nb][h][t][64]
// ---------------------------------------------------------------------------
__global__ __launch_bounds__(256) void rope_split_qk(
    const float* __restrict__ qkv,
    __nv_bfloat16* __restrict__ Qh, __nv_bfloat16* __restrict__ Ql,
    __nv_bfloat16* __restrict__ Kh, __nv_bfloat16* __restrict__ Kl)
{
    const int t0 = blockIdx.x * 64, h = blockIdx.y, nb = blockIdx.z;
    for (int idx = threadIdx.x; idx < 64 * 32; idx += 256) {
        const int tl = idx >> 5, p = idx & 31;
        const int t = t0 + tl;
        const float inv = exp2f(-(float)p * FREQ_C);
        float s, c;
        sincosf((float)t * inv, &s, &c);

        const size_t src = (size_t)(nb * TT + t) * QC + h * HD;
        const size_t dst = ((size_t)(nb * HH + h) * TT + t) * HD;

        const float q1 = qkv[src + p], q2 = qkv[src + p + 32];
        const float qa = (q1 * c - q2 * s) * 0.125f;
        const float qb = (q2 * c + q1 * s) * 0.125f;
        __nv_bfloat16 hh, ll;
        split1(qa, hh, ll);  Qh[dst + p] = hh;       Ql[dst + p] = ll;
        split1(qb, hh, ll);  Qh[dst + p + 32] = hh;  Ql[dst + p + 32] = ll;

        const float k1 = qkv[src + DD + p], k2 = qkv[src + DD + p + 32];
        const float ka = k1 * c - k2 * s;
        const float kb = k2 * c + k1 * s;
        split1(ka, hh, ll);  Kh[dst + p] = hh;       Kl[dst + p] = ll;
        split1(kb, hh, ll);  Kh[dst + p + 32] = hh;  Kl[dst + p + 32] = ll;
    }
}

// ---------------------------------------------------------------------------
// prep 2: V transpose + split -> Vt [nb][h][d][t]
// ---------------------------------------------------------------------------
__global__ __launch_bounds__(256) void vtrans_split(
    const float* __restrict__ qkv,
    __nv_bfloat16* __restrict__ Vth, __nv_bfloat16* __restrict__ Vtl)
{
    __shared__ float tile[64 * 65];
    const int t0 = blockIdx.x * 64, h = blockIdx.y, nb = blockIdx.z;
    for (int idx = threadIdx.x; idx < 64 * 64; idx += 256) {
        const int tl = idx >> 6, d = idx & 63;
        tile[tl * 65 + d] =
            qkv[(size_t)(nb * TT + t0 + tl) * QC + 2 * DD + h * HD + d];
    }
    __syncthreads();
    for (int idx = threadIdx.x; idx < 64 * 64; idx += 256) {
        const int d = idx >> 6, tl = idx & 63;
        const float v = tile[tl * 65 + d];
        __nv_bfloat16 hh, ll;
        split1(v, hh, ll);
        const size_t dst = ((size_t)(nb * HH + h) * HD + d) * TT + t0 + tl;
        Vth[dst] = hh;  Vtl[dst] = ll;
    }
}

// ---------------------------------------------------------------------------
// MMA flash attention (unchanged winner); epilogue writes single fp16.
// ---------------------------------------------------------------------------
__global__ __launch_bounds__(256, 1) void attn_mma(
    const __nv_bfloat16* __restrict__ Qh, const __nv_bfloat16* __restrict__ Ql,
    const __nv_bfloat16* __restrict__ Kh, const __nv_bfloat16* __restrict__ Kl,
    const __nv_bfloat16* __restrict__ Vth, const __nv_bfloat16* __restrict__ Vtl,
    __half* __restrict__ oh)
{
    extern __shared__ char sm[];
    const uint32_t smb = s2u(sm);

    const int tid = threadIdx.x, lane = tid & 31, w = tid >> 5;
    const int i0 = blockIdx.x * 128, h = blockIdx.y, nb = blockIdx.z;
    const size_t qkbase = (size_t)(nb * HH + h) * TT;
    const size_t vbase  = (size_t)(nb * HH + h) * HD;

    const int lrow = lane & 15, half = lane >> 4;
    const int g = lane >> 2, qc = lane & 3;
    const int rl0 = w * 16 + g, rl1 = rl0 + 8;

    for (int idx = tid; idx < 128 * 8; idx += 256) {
        const int r = idx >> 3, c = idx & 7;
        const size_t gq = (qkbase + i0 + r) * HD + c * 8;
        cp16(smb + SM_KH + r * KP + c * 16, Qh + gq);
        cp16(smb + SM_KL + r * KP + c * 16, Ql + gq);
    }
    cp_commit(); cp_wait<0>(); __syncthreads();

    uint32_t qfh[4][4], qfl[4][4];
    {
        const uint32_t aB = smb + (uint32_t)(w * 16 + lrow) * KP + half * 16;
#pragma unroll
        for (int kd = 0; kd < 4; kd++) {
            ldm_x4(qfh[kd][0], qfh[kd][1], qfh[kd][2], qfh[kd][3], aB + kd * 32);
            ldm_x4(qfl[kd][0], qfl[kd][1], qfl[kd][2], qfl[kd][3],
                   aB + SM_KL + kd * 32);
        }
    }
    __syncthreads();

    float of[8][4];
#pragma unroll
    for (int i = 0; i < 8; i++)
#pragma unroll
        for (int j = 0; j < 4; j++) of[i][j] = 0.f;
    float m0 = -1e30f, m1 = -1e30f, l0 = 0.f, l1 = 0.f;

#pragma unroll
    for (int cc = 0; cc < 3; cc++) {
        const int cm = (cc == 0) ? 1 : (cc == 1) ? 0 : 2;
        const int j0 = i0 + (cm - 1) * 128;
        if (j0 < 0 || j0 >= TT) continue;

        for (int idx = tid; idx < 128 * 8; idx += 256) {
            const int r = idx >> 3, c = idx & 7;
            const size_t gk = (qkbase + j0 + r) * HD + c * 8;
            cp16(smb + SM_KH + r * KP + c * 16, Kh + gk);
            cp16(smb + SM_KL + r * KP + c * 16, Kl + gk);
        }
        for (int idx = tid; idx < 64 * 16; idx += 256) {
            const int r = idx >> 4, c = idx & 15;
            const size_t gv = (vbase + r) * TT + j0 + c * 8;
            cp16(smb + SM_VH + r * VP + c * 16, Vth + gv);
            cp16(smb + SM_VL + r * VP + c * 16, Vtl + gv);
        }
        cp_commit(); cp_wait<0>(); __syncthreads();

        float sf[16][4];
#pragma unroll
        for (int i = 0; i < 16; i++)
#pragma unroll
            for (int j = 0; j < 4; j++) sf[i][j] = 0.f;

        const uint32_t bB = smb + (uint32_t)lrow * KP + half * 16;
#pragma unroll
        for (int kd = 0; kd < 4; kd++) {
#pragma unroll
            for (int nt16 = 0; nt16 < 8; nt16++) {
                uint32_t t0, t1, t2, t3;
                uint32_t bh0[2], bh1[2], bl0[2], bl1[2];
                ldm_x4(t0, t1, t2, t3, bB + nt16 * 16 * KP + kd * 32);
                bh0[0] = t0; bh0[1] = t2; bh1[0] = t1; bh1[1] = t3;
                ldm_x4(t0, t1, t2, t3, bB + SM_KL + nt16 * 16 * KP + kd * 32);
                bl0[0] = t0; bl0[1] = t2; bl1[0] = t1; bl1[1] = t3;
                mma_bf16(sf[2 * nt16],     qfh[kd], bh0);
                mma_bf16(sf[2 * nt16],     qfh[kd], bl0);
                mma_bf16(sf[2 * nt16],     qfl[kd], bh0);
                mma_bf16(sf[2 * nt16 + 1], qfh[kd], bh1);
                mma_bf16(sf[2 * nt16 + 1], qfh[kd], bl1);
                mma_bf16(sf[2 * nt16 + 1], qfl[kd], bh1);
            }
        }

        if (cm == 0) {
#pragma unroll
            for (int nt = 0; nt < 16; nt++) {
                const int col = nt * 8 + 2 * qc;
                if (col     <= rl0) sf[nt][0] = -1e30f;
                if (col + 1 <= rl0) sf[nt][1] = -1e30f;
                if (col     <= rl1) sf[nt][2] = -1e30f;
                if (col + 1 <= rl1) sf[nt][3] = -1e30f;
            }
        } else if (cm == 2) {
#pragma unroll
            for (int nt = 0; nt < 16; nt++) {
                const int col = nt * 8 + 2 * qc;
                if (col     > rl0) sf[nt][0] = -1e30f;
                if (col + 1 > rl0) sf[nt][1] = -1e30f;
                if (col     > rl1) sf[nt][2] = -1e30f;
                if (col + 1 > rl1) sf[nt][3] = -1e30f;
            }
        }

        float mx0 = -1e30f, mx1 = -1e30f;
#pragma unroll
        for (int nt = 0; nt < 16; nt++) {
            mx0 = fmaxf(mx0, fmaxf(sf[nt][0], sf[nt][1]));
            mx1 = fmaxf(mx1, fmaxf(sf[nt][2], sf[nt][3]));
        }
        mx0 = fmaxf(mx0, __shfl_xor_sync(0xffffffffu, mx0, 1));
        mx0 = fmaxf(mx0, __shfl_xor_sync(0xffffffffu, mx0, 2));
        mx1 = fmaxf(mx1, __shfl_xor_sync(0xffffffffu, mx1, 1));
        mx1 = fmaxf(mx1, __shfl_xor_sync(0xffffffffu, mx1, 2));
        const float mn0 = fmaxf(m0, mx0), mn1 = fmaxf(m1, mx1);
        const float a0 = __expf(m0 - mn0), a1 = __expf(m1 - mn1);
        m0 = mn0; m1 = mn1;
        float s0 = 0.f, s1 = 0.f;
#pragma unroll
        for (int nt = 0; nt < 16; nt++) {
            sf[nt][0] = __expf(sf[nt][0] - m0);
            sf[nt][1] = __expf(sf[nt][1] - m0);
            sf[nt][2] = __expf(sf[nt][2] - m1);
            sf[nt][3] = __expf(sf[nt][3] - m1);
            s0 += sf[nt][0] + sf[nt][1];
            s1 += sf[nt][2] + sf[nt][3];
        }
        s0 += __shfl_xor_sync(0xffffffffu, s0, 1);
        s0 += __shfl_xor_sync(0xffffffffu, s0, 2);
        s1 += __shfl_xor_sync(0xffffffffu, s1, 1);
        s1 += __shfl_xor_sync(0xffffffffu, s1, 2);
        l0 = l0 * a0 + s0;
        l1 = l1 * a1 + s1;
#pragma unroll
        for (int nt = 0; nt < 8; nt++) {
            of[nt][0] *= a0; of[nt][1] *= a0;
            of[nt][2] *= a1; of[nt][3] *= a1;
        }

        const uint32_t vB = smb + SM_VH + (uint32_t)lrow * VP + half * 16;
#pragma unroll
        for (int kk = 0; kk < 8; kk++) {
            uint32_t ph[4], pl[4];
            packbf(sf[2 * kk][0],     sf[2 * kk][1],     ph[0], pl[0]);
            packbf(sf[2 * kk][2],     sf[2 * kk][3],     ph[1], pl[1]);
            packbf(sf[2 * kk + 1][0], sf[2 * kk + 1][1], ph[2], pl[2]);
            packbf(sf[2 * kk + 1][2], sf[2 * kk + 1][3], ph[3], pl[3]);
#pragma unroll
            for (int nv = 0; nv < 4; nv++) {
                uint32_t t0, t1, t2, t3;
                uint32_t vh0[2], vh1[2], vl0[2], vl1[2];
                ldm_x4(t0, t1, t2, t3, vB + nv * 16 * VP + kk * 32);
                vh0[0] = t0; vh0[1] = t2; vh1[0] = t1; vh1[1] = t3;
                ldm_x4(t0, t1, t2, t3,
                       vB + (SM_VL - SM_VH) + nv * 16 * VP + kk * 32);
                vl0[0] = t0; vl0[1] = t2; vl1[0] = t1; vl1[1] = t3;
                mma_bf16(of[2 * nv],     ph, vh0);
                mma_bf16(of[2 * nv],     ph, vl0);
                mma_bf16(of[2 * nv],     pl, vh0);
                mma_bf16(of[2 * nv + 1], ph, vh1);
                mma_bf16(of[2 * nv + 1], ph, vl1);
                mma_bf16(of[2 * nv + 1], pl, vh1);
            }
        }
        __syncthreads();
    }

    const float i0f = 1.0f / l0, i1f = 1.0f / l1;
    const int tg0 = i0 + rl0, tg1 = i0 + rl1;
#pragma unroll
    for (int nt = 0; nt < 8; nt++) {
        const int col = h * HD + nt * 8 + 2 * qc;
        __half2 h2 = __floats2half2_rn(of[nt][0] * i0f, of[nt][1] * i0f);
        *(uint32_t*)(oh + (size_t)(nb * TT + tg0) * DD + col) =
            *reinterpret_cast<uint32_t*>(&h2);
        h2 = __floats2half2_rn(of[nt][2] * i1f, of[nt][3] * i1f);
        *(uint32_t*)(oh + (size_t)(nb * TT + tg1) * DD + col) =
            *reinterpret_cast<uint32_t*>(&h2);
    }
}

// ---------------------------------------------------------------------------
extern "C" void kernel_launch(void* const* d_in, const int* in_sizes, int n_in,
                              void* d_out, int out_size)
{
    const float* x     = (const float*)d_in[0];
    const float* w_qkv = (const float*)d_in[1];
    const float* w_out = (const float*)d_in[2];
    const float* b_out = (const float*)d_in[3];
    float* out = (float*)d_out;

    float* qkv;  cudaGetSymbolAddress((void**)&qkv, g_qkv);
    __half *xh, *wqh, *woh, *ah;
    __nv_bfloat16 *qh, *ql, *kh, *kl, *vth, *vtl;
    cudaGetSymbolAddress((void**)&xh,  g_xh);
    cudaGetSymbolAddress((void**)&wqh, g_wqh);
    cudaGetSymbolAddress((void**)&woh, g_woh);
    cudaGetSymbolAddress((void**)&ah,  g_ah);
    cudaGetSymbolAddress((void**)&qh,  g_qh);
    cudaGetSymbolAddress((void**)&ql,  g_ql);
    cudaGetSymbolAddress((void**)&kh,  g_kh);
    cudaGetSymbolAddress((void**)&kl,  g_kl);
    cudaGetSymbolAddress((void**)&vth, g_vth);
    cudaGetSymbolAddress((void**)&vtl, g_vtl);

    cudaFuncSetAttribute(gemm_hmma,
                         cudaFuncAttributeMaxDynamicSharedMemorySize, GEMM_SMEM);
    cudaFuncSetAttribute(attn_mma,
                         cudaFuncAttributeMaxDynamicSharedMemorySize, ATTN_SMEM);

    // 1) convert x, w_qkv, w_out to fp16
    {
        int n4 = MR * DD / 4;
        conv_half<<<(n4 + 255) / 256, 256>>>((const float4*)x, (__half2*)xh, n4);
        n4 = QC * DD / 4;
        conv_half<<<(n4 + 255) / 256, 256>>>(
            (const float4*)w_qkv, (__half2*)wqh, n4);
        n4 = DD * DD / 4;
        conv_half<<<(n4 + 255) / 256, 256>>>(
            (const float4*)w_out, (__half2*)woh, n4);
    }

    // 2) QKV projection (1-pass fp16 HMMA)
    {
        dim3 grid(QC / 128, MR / 128);
        gemm_hmma<<<grid, 256, GEMM_SMEM>>>(QC, DD, xh, wqh, nullptr, qkv);
    }

    // 3) prep: RoPE+split Q/K, transpose+split V (bf16)
    {
        dim3 grid(TT / 64, HH, NB);
        rope_split_qk<<<grid, 256>>>(qkv, qh, ql, kh, kl);
        vtrans_split<<<grid, 256>>>(qkv, vth, vtl);
    }

    // 4) MMA flash attention (banded), writes fp16 attn-out
    {
        dim3 grid(TT / 128, HH, NB);
        attn_mma<<<grid, 256, ATTN_SMEM>>>(qh, ql, kh, kl, vth, vtl, ah);
    }

    // 5) output projection (1-pass fp16 HMMA) + bias
    {
        dim3 grid(DD / 128, MR / 128);
        gemm_hmma<<<grid, 256, GEMM_SMEM>>>(DD, DD, ah, woh, b_out, out);
    }
}